// round 4
// baseline (speedup 1.0000x reference)
#include <cuda_runtime.h>
#include <cuda_bf16.h>
#include <cstdint>

typedef unsigned long long u64;
typedef uint32_t u32;

#define DEV_INLINE __device__ __forceinline__

// ------------------------- constants -------------------------
static constexpr int B_ = 4;
static constexpr int C_ = 256;
static constexpr int D_ = 32;     // C/8
static constexpr int N_ = 4096;   // 64*64
static constexpr int BI = 128;    // queries per CTA
static constexpr int BJ = 128;    // keys per j-tile

// scratch (static device globals — allocation-free per harness rules)
__device__ __align__(16) __nv_bfloat16 g_Qt[B_ * N_ * D_];   // [b][n][d]  (transposed)
__device__ __align__(16) __nv_bfloat16 g_Kt[B_ * N_ * D_];   // [b][n][d]
__device__ __align__(16) __nv_bfloat16 g_V [B_ * C_ * N_];   // [b][c][n]

// ------------------------- helpers -------------------------
DEV_INLINE u32 smem_u32(const void* p) {
    u32 a; asm("{ .reg .u64 t; cvta.to.shared.u64 t, %1; cvt.u32.u64 %0, t; }" : "=r"(a) : "l"(p));
    return a;
}
DEV_INLINE u64 pk2(float a, float b) { u64 r; asm("mov.b64 %0, {%1,%2};" : "=l"(r) : "f"(a), "f"(b)); return r; }
DEV_INLINE void upk2(u64 v, float& a, float& b) { asm("mov.b64 {%0,%1}, %2;" : "=f"(a), "=f"(b) : "l"(v)); }
DEV_INLINE void fma2(u64& d, u64 a, u64 b) { asm("fma.rn.f32x2 %0, %1, %2, %0;" : "+l"(d) : "l"(a), "l"(b)); }

DEV_INLINE void ldsm4(u32& r0, u32& r1, u32& r2, u32& r3, u32 addr) {
    asm volatile("ldmatrix.sync.aligned.m8n8.x4.shared.b16 {%0,%1,%2,%3}, [%4];"
                 : "=r"(r0), "=r"(r1), "=r"(r2), "=r"(r3) : "r"(addr));
}
DEV_INLINE void mma16816(float* c, const u32* a, u32 b0, u32 b1) {
    asm volatile(
        "mma.sync.aligned.m16n8k16.row.col.f32.bf16.bf16.f32 "
        "{%0,%1,%2,%3}, {%4,%5,%6,%7}, {%8,%9}, {%0,%1,%2,%3};"
        : "+f"(c[0]), "+f"(c[1]), "+f"(c[2]), "+f"(c[3])
        : "r"(a[0]), "r"(a[1]), "r"(a[2]), "r"(a[3]), "r"(b0), "r"(b1));
}
DEV_INLINE void cpa16(u32 dst, const void* src) {
    asm volatile("cp.async.cg.shared.global [%0], [%1], 16;" :: "r"(dst), "l"(src));
}
#define CP_COMMIT() asm volatile("cp.async.commit_group;" ::: "memory")

// SMEM addressing (bf16), XOR-chunk swizzle for conflict-free-ish ldmatrix.
// Q/K tiles: 64B rows (32 bf16 of d); 16B chunk ^= row&3
DEV_INLINE u32 qkoff(int row, int kcol) {
    return (u32)(row * 64 + ((((kcol >> 3) ^ row) & 3) << 4) + ((kcol & 7) << 1));
}
// P/V tiles: 256B rows (128 bf16 of j); chunk ^= row&7
DEV_INLINE u32 pvoff(int row, int kcol) {
    return (u32)(row * 256 + ((((kcol >> 3) ^ (row & 7)) & 15) << 4) + ((kcol & 7) << 1));
}

// SMEM layout (dynamic)
static constexpr int SM_Q   = 0;        // 128 x 64B  =  8 KB
static constexpr int SM_K0  = 8192;     // 128 x 64B  x2 buffers
static constexpr int SM_K1  = 16384;
static constexpr int SM_V0  = 24576;    // 256 x 256B x2 buffers
static constexpr int SM_V1  = 90112;
static constexpr int SM_P   = 155648;   // 128 x 256B = 32 KB (also f32 out-staging)
static constexpr int SM_L   = 188416;   // float[128][2]
static constexpr int SM_INV = 189440;   // float[128]
static constexpr int SMEM_SZ = 189952;

// ------------------------- projection kernel -------------------------
// dst 0/1 (Q/K, R=32): writes transposed [b][n][32] bf16 rows.
// dst 2   (V, R=256):  writes [b][c][n] bf16.
__global__ __launch_bounds__(256) void proj_kernel(
    const float* __restrict__ x, const float* __restrict__ W,
    const float* __restrict__ bias, int dst, int R, float scale)
{
    const int tid = threadIdx.x;
    const int n  = blockIdx.x * 512 + tid;
    const int r0 = blockIdx.y * 32;
    const int b  = blockIdx.z;

    __shared__ __align__(16) float Ws[256 * 34];   // Ws[c*34 + r]

    for (int idx = tid; idx < 32 * 256; idx += 256) {
        int r = idx >> 8, c = idx & 255;
        Ws[c * 34 + r] = W[(r0 + r) * 256 + c];
    }
    __syncthreads();

    u64 accA[16], accB[16];
#pragma unroll
    for (int k = 0; k < 16; k++) { accA[k] = 0ull; accB[k] = 0ull; }

    const float* xa = x + ((size_t)b * C_) * N_ + n;
    const float* xbp = xa + 256;
#pragma unroll 2
    for (int c = 0; c < 256; c++) {
        float va = xa[(size_t)c * N_];
        float vb = xbp[(size_t)c * N_];
        u64 a2 = pk2(va, va), b2 = pk2(vb, vb);
        const u64* wrow = (const u64*)&Ws[c * 34];
#pragma unroll
        for (int k = 0; k < 16; k++) { fma2(accA[k], wrow[k], a2); fma2(accB[k], wrow[k], b2); }
    }

    if (dst < 2) {
        // transposed store: one contiguous 64B row of 32 bf16 per n
        __nv_bfloat16* base = (dst == 0) ? g_Qt : g_Kt;
#pragma unroll
        for (int half = 0; half < 2; half++) {
            const u64* acc = half ? accB : accA;
            u32 h[16];
#pragma unroll
            for (int k = 0; k < 16; k++) {
                float lo, hi; upk2(acc[k], lo, hi);
                __nv_bfloat162 p = __floats2bfloat162_rn((lo + bias[2 * k]) * scale,
                                                         (hi + bias[2 * k + 1]) * scale);
                h[k] = *(u32*)&p;
            }
            uint4* op = (uint4*)(base + ((size_t)b * N_ + n + half * 256) * 32);
#pragma unroll
            for (int w = 0; w < 4; w++)
                op[w] = make_uint4(h[4 * w], h[4 * w + 1], h[4 * w + 2], h[4 * w + 3]);
        }
    } else {
        __nv_bfloat16* ob = g_V + ((size_t)b * (size_t)R + r0) * N_ + n;
#pragma unroll
        for (int k = 0; k < 16; k++) {
            float lo, hi; upk2(accA[k], lo, hi);
            ob[(size_t)(2 * k) * N_]       = __float2bfloat16_rn((lo + bias[r0 + 2 * k]) * scale);
            ob[(size_t)(2 * k + 1) * N_]   = __float2bfloat16_rn((hi + bias[r0 + 2 * k + 1]) * scale);
            upk2(accB[k], lo, hi);
            ob[(size_t)(2 * k) * N_ + 256]     = __float2bfloat16_rn((lo + bias[r0 + 2 * k]) * scale);
            ob[(size_t)(2 * k + 1) * N_ + 256] = __float2bfloat16_rn((hi + bias[r0 + 2 * k + 1]) * scale);
        }
    }
}

// ------------------------- attention kernel -------------------------
// grid (N/128, B), 256 threads (8 warps), 1 CTA/SM, cp.async double-buffered K/V.
// S phase : warp = (warp>>1)*32 query rows x (warp&1)*64 keys.
// PV phase: warp = (warp>>2)*64 query rows x (warp&3)*64 channels.
__global__ __launch_bounds__(256, 1) void attn_kernel(
    const float* __restrict__ x, const float* __restrict__ gamma,
    float* __restrict__ out)
{
    extern __shared__ __align__(1024) char smem[];
    const u32 sb = smem_u32(smem);
    const int tid  = threadIdx.x;
    const int lane = tid & 31;
    const int warp = tid >> 5;
    const int rr  = lane & 7;
    const int mat = lane >> 3;
    const int i0 = blockIdx.x * BI;
    const int b  = blockIdx.y;

    const char* Qtb = (const char*)(g_Qt + (size_t)b * N_ * D_);
    const char* Ktb = (const char*)(g_Kt + (size_t)b * N_ * D_);
    const char* Vb  = (const char*)(g_V  + (size_t)b * C_ * N_);

    const u32 smK[2] = { sb + SM_K0, sb + SM_K1 };
    const u32 smV[2] = { sb + SM_V0, sb + SM_V1 };

    // ---- staging helpers ----
    // Q tile: rows i0..i0+127, 4 chunks of 16B each
    {
#pragma unroll
        for (int it = 0; it < 2; it++) {
            int idx = tid + it * 256;
            int row = idx >> 2, ch = idx & 3;
            cpa16(sb + SM_Q + row * 64 + (((ch ^ row) & 3) << 4),
                  Qtb + (size_t)(i0 + row) * 64 + ch * 16);
        }
        // K,V tile 0
#pragma unroll
        for (int it = 0; it < 2; it++) {
            int idx = tid + it * 256;
            int row = idx >> 2, ch = idx & 3;
            cpa16(smK[0] + row * 64 + (((ch ^ row) & 3) << 4),
                  Ktb + (size_t)row * 64 + ch * 16);
        }
#pragma unroll
        for (int it = 0; it < 16; it++) {
            int idx = tid + it * 256;
            int c = idx >> 4, ch = idx & 15;
            cpa16(smV[0] + c * 256 + ((ch ^ (c & 7)) << 4),
                  Vb + (size_t)c * (N_ * 2) + ch * 16);
        }
        CP_COMMIT();
    }

    float pv[128];
#pragma unroll
    for (int k = 0; k < 128; k++) pv[k] = 0.0f;
    float lacc[4] = {0.f, 0.f, 0.f, 0.f};
    u32 aq[2][2][4];

    const int mr = (warp >> 1) * 32;      // S-phase query base
    const int jb = (warp & 1) * 64;       // S-phase key base
    const int jh = warp & 1;
    const int qb = (warp >> 2) * 64;      // PV-phase query base
    const int cb = (warp & 3) * 64;       // PV-phase channel base

    for (int t = 0; t < 32; t++) {
        const int buf = t & 1;

        // prefetch tile t+1
        if (t < 31) {
            const int j1 = (t + 1) * BJ;
            const int nb = buf ^ 1;
#pragma unroll
            for (int it = 0; it < 2; it++) {
                int idx = tid + it * 256;
                int row = idx >> 2, ch = idx & 3;
                cpa16(smK[nb] + row * 64 + (((ch ^ row) & 3) << 4),
                      Ktb + (size_t)(j1 + row) * 64 + ch * 16);
            }
#pragma unroll
            for (int it = 0; it < 16; it++) {
                int idx = tid + it * 256;
                int c = idx >> 4, ch = idx & 15;
                cpa16(smV[nb] + c * 256 + ((ch ^ (c & 7)) << 4),
                      Vb + (size_t)c * (N_ * 2) + (size_t)j1 * 2 + ch * 16);
            }
            CP_COMMIT();
            asm volatile("cp.async.wait_group 1;" ::: "memory");
        } else {
            asm volatile("cp.async.wait_group 0;" ::: "memory");
        }
        __syncthreads();

        if (t == 0) {
            // persistent Q fragments (16 regs)
#pragma unroll
            for (int mt = 0; mt < 2; mt++)
#pragma unroll
                for (int kk = 0; kk < 2; kk++)
                    ldsm4(aq[mt][kk][0], aq[mt][kk][1], aq[mt][kk][2], aq[mt][kk][3],
                          sb + SM_Q + qkoff(mr + mt * 16 + rr + ((mat & 1) << 3),
                                            kk * 16 + ((mat >> 1) << 3)));
        }

        // ---- S = Q.K^T (warp: 32q x 64j), exp, P write ----
#pragma unroll
        for (int nbp = 0; nbp < 4; nbp++) {
            const int jcol = jb + nbp * 16;
            u32 bk[2][4];
#pragma unroll
            for (int kk = 0; kk < 2; kk++)
                ldsm4(bk[kk][0], bk[kk][1], bk[kk][2], bk[kk][3],
                      smK[buf] + qkoff(jcol + rr + ((mat >> 1) << 3),
                                       kk * 16 + ((mat & 1) << 3)));
#pragma unroll
            for (int mt = 0; mt < 2; mt++) {
                float s[8] = {0.f,0.f,0.f,0.f,0.f,0.f,0.f,0.f};
#pragma unroll
                for (int kk = 0; kk < 2; kk++) {
                    mma16816(&s[0], aq[mt][kk], bk[kk][0], bk[kk][1]);
                    mma16816(&s[4], aq[mt][kk], bk[kk][2], bk[kk][3]);
                }
                const int q0 = mr + mt * 16 + (lane >> 2);
#pragma unroll
                for (int h2 = 0; h2 < 2; h2++) {   // n-subblock jcol+8*h2
                    float e0 = __expf(s[h2 * 4 + 0]);
                    float e1 = __expf(s[h2 * 4 + 1]);
                    float e2 = __expf(s[h2 * 4 + 2]);
                    float e3 = __expf(s[h2 * 4 + 3]);
                    lacc[mt * 2 + 0] += e0 + e1;
                    lacc[mt * 2 + 1] += e2 + e3;
                    const int jc = jcol + h2 * 8 + (lane & 3) * 2;
                    __nv_bfloat162 p01 = __floats2bfloat162_rn(e0, e1);
                    __nv_bfloat162 p23 = __floats2bfloat162_rn(e2, e3);
                    *(u32*)(smem + SM_P + pvoff(q0,     jc)) = *(u32*)&p01;
                    *(u32*)(smem + SM_P + pvoff(q0 + 8, jc)) = *(u32*)&p23;
                }
            }
        }
        __syncthreads();

        // ---- O += P.V^T (warp: 64q x 64c) ----
#pragma unroll
        for (int kk = 0; kk < 8; kk++) {
            u32 ap[4][4], bv[4][4];
#pragma unroll
            for (int mt = 0; mt < 4; mt++)
                ldsm4(ap[mt][0], ap[mt][1], ap[mt][2], ap[mt][3],
                      sb + SM_P + pvoff(qb + mt * 16 + rr + ((mat & 1) << 3),
                                        kk * 16 + ((mat >> 1) << 3)));
#pragma unroll
            for (int nb = 0; nb < 4; nb++)
                ldsm4(bv[nb][0], bv[nb][1], bv[nb][2], bv[nb][3],
                      smV[buf] + pvoff(cb + nb * 16 + rr + ((mat >> 1) << 3),
                                       kk * 16 + ((mat & 1) << 3)));
#pragma unroll
            for (int mt = 0; mt < 4; mt++)
#pragma unroll
                for (int nb = 0; nb < 4; nb++) {
                    mma16816(&pv[((mt * 4 + nb) * 2 + 0) * 4], ap[mt], bv[nb][0], bv[nb][1]);
                    mma16816(&pv[((mt * 4 + nb) * 2 + 1) * 4], ap[mt], bv[nb][2], bv[nb][3]);
                }
        }
        __syncthreads();   // P + buffers free for next iteration
    }

    // ---- softmax denominator ----
#pragma unroll
    for (int i = 0; i < 4; i++) {
        lacc[i] += __shfl_xor_sync(0xFFFFFFFFu, lacc[i], 1);
        lacc[i] += __shfl_xor_sync(0xFFFFFFFFu, lacc[i], 2);
    }
    if ((lane & 3) == 0) {
#pragma unroll
        for (int i = 0; i < 4; i++) {
            int row = mr + (i >> 1) * 16 + (i & 1) * 8 + (lane >> 2);
            *(float*)(smem + SM_L + (row * 2 + jh) * 4) = lacc[i];
        }
    }
    __syncthreads();
    if (tid < 128) {
        float s = *(float*)(smem + SM_L + (tid * 2) * 4)
                + *(float*)(smem + SM_L + (tid * 2 + 1) * 4);
        *(float*)(smem + SM_INV + tid * 4) = 1.0f / s;
    }
    __syncthreads();

    // ---- epilogue: coalesced via SMEM transpose (reuse SM_P as f32 [256c][16q]) ----
    const float g = gamma[0];
    const float* xb = x   + ((size_t)b * C_) * N_ + i0;
    float*       ob = out + ((size_t)b * C_) * N_ + i0;

    for (int qblk = 0; qblk < 8; qblk++) {
        if ((warp >> 2) == (qblk >> 2)) {
            const int mt = qblk & 3;
#pragma unroll
            for (int nb = 0; nb < 4; nb++)
#pragma unroll
                for (int half = 0; half < 2; half++)
#pragma unroll
                    for (int e2 = 0; e2 < 2; e2++) {
                        int qloc = (lane >> 2) + e2 * 8;
                        int c = cb + nb * 16 + half * 8 + (lane & 3) * 2;
                        float il = *(const float*)(smem + SM_INV + (qblk * 16 + qloc) * 4);
                        float v0 = pv[((mt * 4 + nb) * 2 + half) * 4 + e2 * 2 + 0];
                        float v1 = pv[((mt * 4 + nb) * 2 + half) * 4 + e2 * 2 + 1];
                        *(float*)(smem + SM_P + (c * 16 + qloc) * 4)       = g * v0 * il;
                        *(float*)(smem + SM_P + ((c + 1) * 16 + qloc) * 4) = g * v1 * il;
                    }
        }
        __syncthreads();
#pragma unroll
        for (int i = 0; i < 16; i++) {
            int e = i * 256 + tid;
            int c = e >> 4, q = e & 15;
            int qg = qblk * 16 + q;
            ob[(size_t)c * N_ + qg] = *(const float*)(smem + SM_P + (c * 16 + q) * 4)
                                    + xb[(size_t)c * N_ + qg];
        }
        __syncthreads();
    }
}

// ------------------------- launch -------------------------
extern "C" void kernel_launch(void* const* d_in, const int* in_sizes, int n_in,
                              void* d_out, int out_size)
{
    (void)in_sizes; (void)n_in; (void)out_size;
    const float* x     = (const float*)d_in[0];
    const float* Wq    = (const float*)d_in[1];
    const float* bq    = (const float*)d_in[2];
    const float* Wk    = (const float*)d_in[3];
    const float* bk    = (const float*)d_in[4];
    const float* Wv    = (const float*)d_in[5];
    const float* bv    = (const float*)d_in[6];
    const float* gamma = (const float*)d_in[7];
    float* out = (float*)d_out;

    const float qscale = 1.0f / 16.0f;   // 1/sqrt(C) folded into Q

    cudaFuncSetAttribute(attn_kernel, cudaFuncAttributeMaxDynamicSharedMemorySize, SMEM_SZ);

    dim3 blk(256);
    proj_kernel<<<dim3(N_ / 512, 1, B_), blk>>>(x, Wq, bq, 0, D_, qscale);
    proj_kernel<<<dim3(N_ / 512, 1, B_), blk>>>(x, Wk, bk, 1, D_, 1.0f);
    proj_kernel<<<dim3(N_ / 512, C_ / 32, B_), blk>>>(x, Wv, bv, 2, C_, 1.0f);
    attn_kernel<<<dim3(N_ / BI, B_), blk, SMEM_SZ>>>(x, gamma, out);
}

// round 5
// speedup vs baseline: 2.9710x; 2.9710x over previous
#include <cuda_runtime.h>
#include <cuda_bf16.h>
#include <cstdint>

typedef unsigned long long u64;
typedef uint32_t u32;

#define DEV_INLINE __device__ __forceinline__

// ------------------------- constants -------------------------
static constexpr int B_ = 4;
static constexpr int C_ = 256;
static constexpr int D_ = 32;     // C/8
static constexpr int N_ = 4096;   // 64*64
static constexpr int BI = 64;     // queries per CTA
static constexpr int BJ = 128;    // keys per j-tile

// scratch (static device globals — allocation-free per harness rules)
__device__ __align__(16) __nv_bfloat16 g_Qt[B_ * N_ * D_];   // [b][n][d] transposed
__device__ __align__(16) __nv_bfloat16 g_Kt[B_ * N_ * D_];   // [b][n][d]
__device__ __align__(16) __nv_bfloat16 g_V [B_ * C_ * N_];   // [b][c][n]

// ------------------------- helpers -------------------------
DEV_INLINE u32 smem_u32(const void* p) {
    u32 a; asm("{ .reg .u64 t; cvta.to.shared.u64 t, %1; cvt.u32.u64 %0, t; }" : "=r"(a) : "l"(p));
    return a;
}
DEV_INLINE u64 pk2(float a, float b) { u64 r; asm("mov.b64 %0, {%1,%2};" : "=l"(r) : "f"(a), "f"(b)); return r; }
DEV_INLINE void upk2(u64 v, float& a, float& b) { asm("mov.b64 {%0,%1}, %2;" : "=f"(a), "=f"(b) : "l"(v)); }
DEV_INLINE void fma2(u64& d, u64 a, u64 b) { asm("fma.rn.f32x2 %0, %1, %2, %0;" : "+l"(d) : "l"(a), "l"(b)); }

DEV_INLINE void ldsm4(u32& r0, u32& r1, u32& r2, u32& r3, u32 addr) {
    asm volatile("ldmatrix.sync.aligned.m8n8.x4.shared.b16 {%0,%1,%2,%3}, [%4];"
                 : "=r"(r0), "=r"(r1), "=r"(r2), "=r"(r3) : "r"(addr));
}
DEV_INLINE void mma16816(float* c, const u32* a, u32 b0, u32 b1) {
    asm volatile(
        "mma.sync.aligned.m16n8k16.row.col.f32.bf16.bf16.f32 "
        "{%0,%1,%2,%3}, {%4,%5,%6,%7}, {%8,%9}, {%0,%1,%2,%3};"
        : "+f"(c[0]), "+f"(c[1]), "+f"(c[2]), "+f"(c[3])
        : "r"(a[0]), "r"(a[1]), "r"(a[2]), "r"(a[3]), "r"(b0), "r"(b1));
}
DEV_INLINE void cpa16(u32 dst, const void* src) {
    asm volatile("cp.async.cg.shared.global [%0], [%1], 16;" :: "r"(dst), "l"(src));
}
#define CP_COMMIT() asm volatile("cp.async.commit_group;" ::: "memory")
#define CP_WAIT(n)  asm volatile("cp.async.wait_group %0;" :: "n"(n) : "memory")

// SMEM addressing (bf16), XOR-chunk swizzle for conflict-free ldmatrix.
// Q/K tiles: 64B rows (32 bf16 of d); 16B chunk ^= row&3
DEV_INLINE u32 qkoff(int row, int kcol) {
    return (u32)(row * 64 + ((((kcol >> 3) ^ row) & 3) << 4) + ((kcol & 7) << 1));
}
// P/V tiles: 256B rows (128 bf16 of j); chunk ^= row&7
DEV_INLINE u32 pvoff(int row, int kcol) {
    return (u32)(row * 256 + ((((kcol >> 3) ^ (row & 7)) & 15) << 4) + ((kcol & 7) << 1));
}

// SMEM layout (dynamic, bytes)
static constexpr int SM_Q   = 0;        // 64  x 64B  =  4 KB
static constexpr int SM_K0  = 4096;     // 128 x 64B
static constexpr int SM_K1  = 12288;    // 128 x 64B
static constexpr int SM_V   = 20480;    // 256 x 256B = 64 KB (single buffer)
static constexpr int SM_P   = 86016;    // 64 x 256B = 16 KB tile; 17.4 KB epi reuse
static constexpr int SM_L   = 104448;   // float[64][2]
static constexpr int SM_INV = 104960;   // float[64]
static constexpr int SMEM_SZ = 105216;

// ------------------------- unified projection kernel -------------------------
// grid (N/512, 10, B): y<8 -> V rows y*32; y==8 -> Q (transposed, scaled); y==9 -> K (transposed)
__global__ __launch_bounds__(256) void proj_kernel(
    const float* __restrict__ x,
    const float* __restrict__ Wq, const float* __restrict__ bq,
    const float* __restrict__ Wk, const float* __restrict__ bk,
    const float* __restrict__ Wv, const float* __restrict__ bv)
{
    const int tid = threadIdx.x;
    const int n  = blockIdx.x * 512 + tid;
    const int y  = blockIdx.y;
    const int b  = blockIdx.z;

    const float* W; const float* bias; int r0; float scale; int mode;
    if (y < 8)       { W = Wv; bias = bv; r0 = y * 32; scale = 1.0f;        mode = 0; }
    else if (y == 8) { W = Wq; bias = bq; r0 = 0;      scale = 1.0f/16.0f;  mode = 1; }
    else             { W = Wk; bias = bk; r0 = 0;      scale = 1.0f;        mode = 2; }

    __shared__ __align__(16) float Ws[256 * 34];   // Ws[c*34 + r]

    for (int idx = tid; idx < 32 * 256; idx += 256) {
        int r = idx >> 8, c = idx & 255;
        Ws[c * 34 + r] = W[(r0 + r) * 256 + c];
    }
    __syncthreads();

    u64 accA[16], accB[16];
#pragma unroll
    for (int k = 0; k < 16; k++) { accA[k] = 0ull; accB[k] = 0ull; }

    const float* xa  = x + ((size_t)b * C_) * N_ + n;
    const float* xbp = xa + 256;
#pragma unroll 2
    for (int c = 0; c < 256; c++) {
        float va = xa[(size_t)c * N_];
        float vb = xbp[(size_t)c * N_];
        u64 a2 = pk2(va, va), b2 = pk2(vb, vb);
        const u64* wrow = (const u64*)&Ws[c * 34];
#pragma unroll
        for (int k = 0; k < 16; k++) { fma2(accA[k], wrow[k], a2); fma2(accB[k], wrow[k], b2); }
    }

    if (mode == 0) {
        __nv_bfloat16* ob = g_V + ((size_t)b * C_ + r0) * N_ + n;
#pragma unroll
        for (int k = 0; k < 16; k++) {
            float lo, hi; upk2(accA[k], lo, hi);
            ob[(size_t)(2 * k) * N_]     = __float2bfloat16_rn(lo + bias[r0 + 2 * k]);
            ob[(size_t)(2 * k + 1) * N_] = __float2bfloat16_rn(hi + bias[r0 + 2 * k + 1]);
            upk2(accB[k], lo, hi);
            ob[(size_t)(2 * k) * N_ + 256]     = __float2bfloat16_rn(lo + bias[r0 + 2 * k]);
            ob[(size_t)(2 * k + 1) * N_ + 256] = __float2bfloat16_rn(hi + bias[r0 + 2 * k + 1]);
        }
    } else {
        __nv_bfloat16* base = (mode == 1) ? g_Qt : g_Kt;
#pragma unroll
        for (int half = 0; half < 2; half++) {
            const u64* acc = half ? accB : accA;
            u32 h[16];
#pragma unroll
            for (int k = 0; k < 16; k++) {
                float lo, hi; upk2(acc[k], lo, hi);
                __nv_bfloat162 p = __floats2bfloat162_rn((lo + bias[2 * k]) * scale,
                                                         (hi + bias[2 * k + 1]) * scale);
                h[k] = *(u32*)&p;
            }
            uint4* op = (uint4*)(base + ((size_t)b * N_ + n + half * 256) * 32);
#pragma unroll
            for (int w = 0; w < 4; w++)
                op[w] = make_uint4(h[4 * w], h[4 * w + 1], h[4 * w + 2], h[4 * w + 3]);
        }
    }
}

// ------------------------- attention kernel -------------------------
// grid (N/64, B), 256 threads (8 warps), 2 CTAs/SM.
// S phase : warp = (warp>>1)*16 query rows x (warp&1)*64 keys.
// PV phase: warp owns channels [warp*32, warp*32+32), all 64 queries, K=128.
__global__ __launch_bounds__(256, 2) void attn_kernel(
    const float* __restrict__ x, const float* __restrict__ gamma,
    float* __restrict__ out)
{
    extern __shared__ __align__(1024) char smem[];
    const u32 sb = smem_u32(smem);
    const int tid  = threadIdx.x;
    const int lane = tid & 31;
    const int warp = tid >> 5;
    const int rr  = lane & 7;
    const int mat = lane >> 3;
    const int i0 = blockIdx.x * BI;
    const int b  = blockIdx.y;

    const char* Qtb = (const char*)(g_Qt + (size_t)b * N_ * D_);
    const char* Ktb = (const char*)(g_Kt + (size_t)b * N_ * D_);
    const char* Vb  = (const char*)(g_V  + (size_t)b * C_ * N_);

    const u32 smK[2] = { sb + SM_K0, sb + SM_K1 };

    // ---- pre-loop staging: Q + K(0) [group], V(0) [group] ----
    {
        // Q: 64 rows x 4 x 16B (1 op/thread)
        int row = tid >> 2, ch = tid & 3;
        cpa16(sb + SM_Q + row * 64 + (((ch ^ row) & 3) << 4),
              Qtb + (size_t)(i0 + row) * 64 + ch * 16);
        // K0: 128 rows x 4 x 16B (2 ops/thread)
#pragma unroll
        for (int it = 0; it < 2; it++) {
            int idx = tid + it * 256;
            int kr = idx >> 2, kc = idx & 3;
            cpa16(smK[0] + kr * 64 + (((kc ^ kr) & 3) << 4),
                  Ktb + (size_t)kr * 64 + kc * 16);
        }
        CP_COMMIT();
        // V0: 256 c x 16 x 16B (16 ops/thread)
#pragma unroll
        for (int it = 0; it < 16; it++) {
            int idx = tid + it * 256;
            int c = idx >> 4, vc = idx & 15;
            cpa16(sb + SM_V + c * 256 + ((vc ^ (c & 7)) << 4),
                  Vb + (size_t)c * (N_ * 2) + vc * 16);
        }
        CP_COMMIT();
    }

    float pv[64];
#pragma unroll
    for (int k = 0; k < 64; k++) pv[k] = 0.0f;
    float lacc0 = 0.0f, lacc1 = 0.0f;
    u32 aq[8];

    const int mr = (warp >> 1) * 16;   // S-phase query base
    const int jb = (warp & 1) * 64;    // S-phase key base
    const int jh = warp & 1;
    const int cb = warp * 32;          // PV-phase channel base

    for (int t = 0; t < 32; t++) {
        const int buf = t & 1;

        if (t < 31) {
            // prefetch K(t+1) into other K buffer (free: K(t-1) consumed)
            const int j1 = (t + 1) * BJ;
#pragma unroll
            for (int it = 0; it < 2; it++) {
                int idx = tid + it * 256;
                int kr = idx >> 2, kc = idx & 3;
                cpa16(smK[buf ^ 1] + kr * 64 + (((kc ^ kr) & 3) << 4),
                      Ktb + (size_t)(j1 + kr) * 64 + kc * 16);
            }
            CP_COMMIT();
            CP_WAIT(1);    // all but newest: K(t) + V(t) arrived
        } else {
            CP_WAIT(0);
        }
        __syncthreads();

        if (t == 0) {
            // persistent Q fragments (16q x 32k)
#pragma unroll
            for (int kk = 0; kk < 2; kk++)
                ldsm4(aq[kk * 4 + 0], aq[kk * 4 + 1], aq[kk * 4 + 2], aq[kk * 4 + 3],
                      sb + SM_Q + qkoff(mr + rr + ((mat & 1) << 3),
                                        kk * 16 + ((mat >> 1) << 3)));
        }

        // ---- S = Q.K^T (warp: 16q x 64j), exp, bf16 P write ----
#pragma unroll
        for (int nbp = 0; nbp < 4; nbp++) {
            const int jcol = jb + nbp * 16;
            u32 bk[2][4];
#pragma unroll
            for (int kk = 0; kk < 2; kk++)
                ldsm4(bk[kk][0], bk[kk][1], bk[kk][2], bk[kk][3],
                      smK[buf] + qkoff(jcol + rr + ((mat >> 1) << 3),
                                       kk * 16 + ((mat & 1) << 3)));
            float s[8] = {0.f,0.f,0.f,0.f,0.f,0.f,0.f,0.f};
#pragma unroll
            for (int kk = 0; kk < 2; kk++) {
                mma16816(&s[0], &aq[kk * 4], bk[kk][0], bk[kk][1]);
                mma16816(&s[4], &aq[kk * 4], bk[kk][2], bk[kk][3]);
            }
            const int q0 = mr + (lane >> 2);
#pragma unroll
            for (int h2 = 0; h2 < 2; h2++) {
                float e0 = __expf(s[h2 * 4 + 0]);
                float e1 = __expf(s[h2 * 4 + 1]);
                float e2 = __expf(s[h2 * 4 + 2]);
                float e3 = __expf(s[h2 * 4 + 3]);
                lacc0 += e0 + e1;
                lacc1 += e2 + e3;
                const int jc = jcol + h2 * 8 + (lane & 3) * 2;
                __nv_bfloat162 p01 = __floats2bfloat162_rn(e0, e1);
                __nv_bfloat162 p23 = __floats2bfloat162_rn(e2, e3);
                *(u32*)(smem + SM_P + pvoff(q0,     jc)) = *(u32*)&p01;
                *(u32*)(smem + SM_P + pvoff(q0 + 8, jc)) = *(u32*)&p23;
            }
        }
        __syncthreads();   // P ready (V already arrived)

        // ---- O += P.V^T (warp: 64q x 32c) ----
#pragma unroll
        for (int kk = 0; kk < 8; kk++) {
            u32 ap[4][4];
#pragma unroll
            for (int mt = 0; mt < 4; mt++)
                ldsm4(ap[mt][0], ap[mt][1], ap[mt][2], ap[mt][3],
                      sb + SM_P + pvoff(mt * 16 + rr + ((mat & 1) << 3),
                                        kk * 16 + ((mat >> 1) << 3)));
#pragma unroll
            for (int np = 0; np < 2; np++) {
                u32 b0, b1, b2, b3;
                ldsm4(b0, b1, b2, b3,
                      sb + SM_V + pvoff(cb + np * 16 + rr + ((mat >> 1) << 3),
                                        kk * 16 + ((mat & 1) << 3)));
#pragma unroll
                for (int mt = 0; mt < 4; mt++) {
                    mma16816(&pv[(mt * 4 + np * 2) * 4],     ap[mt], b0, b1);
                    mma16816(&pv[(mt * 4 + np * 2 + 1) * 4], ap[mt], b2, b3);
                }
            }
        }
        __syncthreads();   // V + P consumed

        if (t < 31) {
            // stage V(t+1); waited before next tile's S phase
            const int j1 = (t + 1) * BJ;
#pragma unroll
            for (int it = 0; it < 16; it++) {
                int idx = tid + it * 256;
                int c = idx >> 4, vc = idx & 15;
                cpa16(sb + SM_V + c * 256 + ((vc ^ (c & 7)) << 4),
                      Vb + (size_t)c * (N_ * 2) + (size_t)j1 * 2 + vc * 16);
            }
            CP_COMMIT();
        }
    }

    // ---- softmax denominator ----
    lacc0 += __shfl_xor_sync(0xFFFFFFFFu, lacc0, 1);
    lacc0 += __shfl_xor_sync(0xFFFFFFFFu, lacc0, 2);
    lacc1 += __shfl_xor_sync(0xFFFFFFFFu, lacc1, 1);
    lacc1 += __shfl_xor_sync(0xFFFFFFFFu, lacc1, 2);
    if ((lane & 3) == 0) {
        const int q0 = mr + (lane >> 2);
        *(float*)(smem + SM_L + (q0 * 2 + jh) * 4)       = lacc0;
        *(float*)(smem + SM_L + ((q0 + 8) * 2 + jh) * 4) = lacc1;
    }
    __syncthreads();
    if (tid < 64) {
        float s = *(float*)(smem + SM_L + (tid * 2) * 4)
                + *(float*)(smem + SM_L + (tid * 2 + 1) * 4);
        *(float*)(smem + SM_INV + tid * 4) = 1.0f / s;
    }
    __syncthreads();

    // ---- epilogue: coalesced via SMEM transpose (reuse SM_P as f32 [256c][17]) ----
    const float g = gamma[0];
    const float* xb = x   + ((size_t)b * C_) * N_ + i0;
    float*       ob = out + ((size_t)b * C_) * N_ + i0;

    for (int qblk = 0; qblk < 4; qblk++) {
        const int mt = qblk;
#pragma unroll
        for (int np = 0; np < 2; np++)
#pragma unroll
            for (int h = 0; h < 2; h++)
#pragma unroll
                for (int e2 = 0; e2 < 2; e2++) {
                    int qloc = (lane >> 2) + e2 * 8;
                    int c = cb + np * 16 + h * 8 + (lane & 3) * 2;
                    float il = *(const float*)(smem + SM_INV + (qblk * 16 + qloc) * 4);
                    float v0 = pv[(mt * 4 + np * 2 + h) * 4 + e2 * 2 + 0];
                    float v1 = pv[(mt * 4 + np * 2 + h) * 4 + e2 * 2 + 1];
                    *(float*)(smem + SM_P + (c * 17 + qloc) * 4)       = g * v0 * il;
                    *(float*)(smem + SM_P + ((c + 1) * 17 + qloc) * 4) = g * v1 * il;
                }
        __syncthreads();
#pragma unroll
        for (int i = 0; i < 16; i++) {
            int e = i * 256 + tid;
            int c = e >> 4, q = e & 15;
            int qg = qblk * 16 + q;
            ob[(size_t)c * N_ + qg] = *(const float*)(smem + SM_P + (c * 17 + q) * 4)
                                    + xb[(size_t)c * N_ + qg];
        }
        __syncthreads();
    }
}

// ------------------------- launch -------------------------
extern "C" void kernel_launch(void* const* d_in, const int* in_sizes, int n_in,
                              void* d_out, int out_size)
{
    (void)in_sizes; (void)n_in; (void)out_size;
    const float* x     = (const float*)d_in[0];
    const float* Wq    = (const float*)d_in[1];
    const float* bq    = (const float*)d_in[2];
    const float* Wk    = (const float*)d_in[3];
    const float* bk    = (const float*)d_in[4];
    const float* Wv    = (const float*)d_in[5];
    const float* bv    = (const float*)d_in[6];
    const float* gamma = (const float*)d_in[7];
    float* out = (float*)d_out;

    cudaFuncSetAttribute(attn_kernel, cudaFuncAttributeMaxDynamicSharedMemorySize, SMEM_SZ);

    dim3 blk(256);
    proj_kernel<<<dim3(N_ / 512, 10, B_), blk>>>(x, Wq, bq, Wk, bk, Wv, bv);
    attn_kernel<<<dim3(N_ / BI, B_), blk, SMEM_SZ>>>(x, gamma, out);
}

// round 8
// speedup vs baseline: 3.0580x; 1.0293x over previous
#include <cuda_runtime.h>
#include <cuda_bf16.h>
#include <cstdint>

typedef unsigned long long u64;
typedef uint32_t u32;

#define DEV_INLINE __device__ __forceinline__

// ------------------------- constants -------------------------
static constexpr int B_ = 4;
static constexpr int C_ = 256;
static constexpr int D_ = 32;     // C/8
static constexpr int N_ = 4096;   // 64*64
static constexpr int BI = 64;     // queries per CTA
static constexpr int BJ = 128;    // keys per j-tile

// scratch (static device globals — allocation-free per harness rules)
__device__ __align__(16) __nv_bfloat16 g_Qt[B_ * N_ * D_];   // [b][n][d] transposed
__device__ __align__(16) __nv_bfloat16 g_Kt[B_ * N_ * D_];   // [b][n][d]
__device__ __align__(16) __nv_bfloat16 g_V [B_ * C_ * N_];   // [b][c][n]

// ------------------------- helpers -------------------------
DEV_INLINE u32 smem_u32(const void* p) {
    u32 a; asm("{ .reg .u64 t; cvta.to.shared.u64 t, %1; cvt.u32.u64 %0, t; }" : "=r"(a) : "l"(p));
    return a;
}
DEV_INLINE u64 pk2(float a, float b) { u64 r; asm("mov.b64 %0, {%1,%2};" : "=l"(r) : "f"(a), "f"(b)); return r; }
DEV_INLINE void upk2(u64 v, float& a, float& b) { asm("mov.b64 {%0,%1}, %2;" : "=f"(a), "=f"(b) : "l"(v)); }
DEV_INLINE void fma2(u64& d, u64 a, u64 b) { asm("fma.rn.f32x2 %0, %1, %2, %0;" : "+l"(d) : "l"(a), "l"(b)); }

DEV_INLINE void ldsm4(u32& r0, u32& r1, u32& r2, u32& r3, u32 addr) {
    asm volatile("ldmatrix.sync.aligned.m8n8.x4.shared.b16 {%0,%1,%2,%3}, [%4];"
                 : "=r"(r0), "=r"(r1), "=r"(r2), "=r"(r3) : "r"(addr));
}
DEV_INLINE void mma16816(float* c, const u32* a, u32 b0, u32 b1) {
    asm volatile(
        "mma.sync.aligned.m16n8k16.row.col.f32.bf16.bf16.f32 "
        "{%0,%1,%2,%3}, {%4,%5,%6,%7}, {%8,%9}, {%0,%1,%2,%3};"
        : "+f"(c[0]), "+f"(c[1]), "+f"(c[2]), "+f"(c[3])
        : "r"(a[0]), "r"(a[1]), "r"(a[2]), "r"(a[3]), "r"(b0), "r"(b1));
}
DEV_INLINE void cpa16(u32 dst, const void* src) {
    asm volatile("cp.async.cg.shared.global [%0], [%1], 16;" :: "r"(dst), "l"(src));
}
#define CP_COMMIT() asm volatile("cp.async.commit_group;" ::: "memory")
#define CP_WAIT(n)  asm volatile("cp.async.wait_group %0;" :: "n"(n) : "memory")

// SMEM addressing (bf16), XOR-chunk swizzle for conflict-free ldmatrix.
DEV_INLINE u32 qkoff(int row, int kcol) {
    return (u32)(row * 64 + ((((kcol >> 3) ^ row) & 3) << 4) + ((kcol & 7) << 1));
}
DEV_INLINE u32 pvoff(int row, int kcol) {
    return (u32)(row * 256 + ((((kcol >> 3) ^ (row & 7)) & 15) << 4) + ((kcol & 7) << 1));
}

// SMEM layout (dynamic, bytes). P double-buffered; Q aliased into P1
// (Q consumed into registers at t=0; P1 first written at t=1).
static constexpr int SM_P1  = 0;        // 64 x 256B = 16 KB   (Q = first 4 KB)
static constexpr int SM_Q   = 0;
static constexpr int SM_P0  = 16384;    // 64 x 256B
static constexpr int SM_K0  = 32768;    // 128 x 64B
static constexpr int SM_K1  = 40960;    // 128 x 64B
static constexpr int SM_V   = 49152;    // 256 x 256B = 64 KB (single buffer)
static constexpr int SM_L   = 114688;   // float[64][2]
static constexpr int SM_INV = 115200;   // float[64]
static constexpr int SMEM_SZ = 115456;  // x2 CTAs = 225.5 KB/SM

// ------------------------- unified projection kernel -------------------------
__global__ __launch_bounds__(256) void proj_kernel(
    const float* __restrict__ x,
    const float* __restrict__ Wq, const float* __restrict__ bq,
    const float* __restrict__ Wk, const float* __restrict__ bk,
    const float* __restrict__ Wv, const float* __restrict__ bv)
{
    const int tid = threadIdx.x;
    const int n0 = blockIdx.x * 512 + tid * 2;
    const int y  = blockIdx.y;
    const int b  = blockIdx.z;

    const float* W; const float* bias; int r0; float scale; int mode;
    if (y < 8)       { W = Wv; bias = bv; r0 = y * 32; scale = 1.0f;        mode = 0; }
    else if (y == 8) { W = Wq; bias = bq; r0 = 0;      scale = 1.0f/16.0f;  mode = 1; }
    else             { W = Wk; bias = bk; r0 = 0;      scale = 1.0f;        mode = 2; }

    __shared__ __align__(16) float Ws[256 * 34];   // Ws[c*34 + r]

    for (int idx = tid; idx < 32 * 256; idx += 256) {
        int r = idx >> 8, c = idx & 255;
        Ws[c * 34 + r] = W[(r0 + r) * 256 + c];
    }
    __syncthreads();

    u64 accA[16], accB[16];
#pragma unroll
    for (int k = 0; k < 16; k++) { accA[k] = 0ull; accB[k] = 0ull; }

    const float* xa = x + ((size_t)b * C_) * N_ + n0;
#pragma unroll 4
    for (int c = 0; c < 256; c++) {
        float2 v = *(const float2*)&xa[(size_t)c * N_];
        u64 a2 = pk2(v.x, v.x), b2 = pk2(v.y, v.y);
        const u64* wrow = (const u64*)&Ws[c * 34];
#pragma unroll
        for (int k = 0; k < 16; k++) { fma2(accA[k], wrow[k], a2); fma2(accB[k], wrow[k], b2); }
    }

    if (mode == 0) {
        __nv_bfloat16* ob = g_V + ((size_t)b * C_ + r0) * N_ + n0;
#pragma unroll
        for (int k = 0; k < 16; k++) {
            float alo, ahi, blo, bhi;
            upk2(accA[k], alo, ahi); upk2(accB[k], blo, bhi);
            __nv_bfloat162 p0 = __floats2bfloat162_rn(alo + bias[r0 + 2 * k], blo + bias[r0 + 2 * k]);
            __nv_bfloat162 p1 = __floats2bfloat162_rn(ahi + bias[r0 + 2 * k + 1], bhi + bias[r0 + 2 * k + 1]);
            *(u32*)&ob[(size_t)(2 * k) * N_]     = *(u32*)&p0;
            *(u32*)&ob[(size_t)(2 * k + 1) * N_] = *(u32*)&p1;
        }
    } else {
        __nv_bfloat16* base = (mode == 1) ? g_Qt : g_Kt;
#pragma unroll
        for (int half = 0; half < 2; half++) {
            const u64* acc = half ? accB : accA;
            u32 h[16];
#pragma unroll
            for (int k = 0; k < 16; k++) {
                float lo, hi; upk2(acc[k], lo, hi);
                __nv_bfloat162 p = __floats2bfloat162_rn((lo + bias[2 * k]) * scale,
                                                         (hi + bias[2 * k + 1]) * scale);
                h[k] = *(u32*)&p;
            }
            uint4* op = (uint4*)(base + ((size_t)b * N_ + n0 + half) * 32);
#pragma unroll
            for (int w = 0; w < 4; w++)
                op[w] = make_uint4(h[4 * w], h[4 * w + 1], h[4 * w + 2], h[4 * w + 3]);
        }
    }
}

// ------------------------- attention device helpers -------------------------
struct AttnCtx {
    u32 sb; int tid, lane, warp, rr, mat, mr, jb, cb;
};

DEV_INLINE void s_phase(const AttnCtx& cx, char* smem, u32 kbuf, u32 pofs,
                        const u32 aq[8], float& lacc0, float& lacc1)
{
#pragma unroll
    for (int nbp = 0; nbp < 4; nbp++) {
        const int jcol = cx.jb + nbp * 16;
        u32 bk[2][4];
#pragma unroll
        for (int kk = 0; kk < 2; kk++)
            ldsm4(bk[kk][0], bk[kk][1], bk[kk][2], bk[kk][3],
                  kbuf + qkoff(jcol + cx.rr + ((cx.mat >> 1) << 3),
                               kk * 16 + ((cx.mat & 1) << 3)));
        float s[8] = {0.f,0.f,0.f,0.f,0.f,0.f,0.f,0.f};
#pragma unroll
        for (int kk = 0; kk < 2; kk++) {
            mma16816(&s[0], &aq[kk * 4], bk[kk][0], bk[kk][1]);
            mma16816(&s[4], &aq[kk * 4], bk[kk][2], bk[kk][3]);
        }
        const int q0 = cx.mr + (cx.lane >> 2);
#pragma unroll
        for (int h2 = 0; h2 < 2; h2++) {
            float e0 = __expf(s[h2 * 4 + 0]);
            float e1 = __expf(s[h2 * 4 + 1]);
            float e2 = __expf(s[h2 * 4 + 2]);
            float e3 = __expf(s[h2 * 4 + 3]);
            lacc0 += e0 + e1;
            lacc1 += e2 + e3;
            const int jc = jcol + h2 * 8 + (cx.lane & 3) * 2;
            __nv_bfloat162 p01 = __floats2bfloat162_rn(e0, e1);
            __nv_bfloat162 p23 = __floats2bfloat162_rn(e2, e3);
            *(u32*)(smem + pofs + pvoff(q0,     jc)) = *(u32*)&p01;
            *(u32*)(smem + pofs + pvoff(q0 + 8, jc)) = *(u32*)&p23;
        }
    }
}

DEV_INLINE void pv_phase(const AttnCtx& cx, u32 pbuf, u32 vbuf, float pv[64])
{
#pragma unroll
    for (int kk = 0; kk < 8; kk++) {
        u32 ap[4][4];
#pragma unroll
        for (int mt = 0; mt < 4; mt++)
            ldsm4(ap[mt][0], ap[mt][1], ap[mt][2], ap[mt][3],
                  pbuf + pvoff(mt * 16 + cx.rr + ((cx.mat & 1) << 3),
                               kk * 16 + ((cx.mat >> 1) << 3)));
#pragma unroll
        for (int np = 0; np < 2; np++) {
            u32 b0, b1, b2, b3;
            ldsm4(b0, b1, b2, b3,
                  vbuf + pvoff(cx.cb + np * 16 + cx.rr + ((cx.mat >> 1) << 3),
                               kk * 16 + ((cx.mat & 1) << 3)));
#pragma unroll
            for (int mt = 0; mt < 4; mt++) {
                mma16816(&pv[(mt * 4 + np * 2) * 4],     ap[mt], b0, b1);
                mma16816(&pv[(mt * 4 + np * 2 + 1) * 4], ap[mt], b2, b3);
            }
        }
    }
}

DEV_INLINE void stage_K(const AttnCtx& cx, u32 kbuf, const char* Ktb, int j0) {
#pragma unroll
    for (int it = 0; it < 2; it++) {
        int idx = cx.tid + it * 256;
        int kr = idx >> 2, kc = idx & 3;
        cpa16(kbuf + kr * 64 + (((kc ^ kr) & 3) << 4),
              Ktb + (size_t)(j0 + kr) * 64 + kc * 16);
    }
}
DEV_INLINE void stage_V(const AttnCtx& cx, u32 vbuf, const char* Vb, int j0) {
#pragma unroll
    for (int it = 0; it < 16; it++) {
        int idx = cx.tid + it * 256;
        int c = idx >> 4, vc = idx & 15;
        cpa16(vbuf + c * 256 + ((vc ^ (c & 7)) << 4),
              Vb + (size_t)c * (N_ * 2) + (size_t)j0 * 2 + vc * 16);
    }
}

// ------------------------- attention kernel -------------------------
// grid (N/64, B), 256 threads (8 warps), 2 CTAs/SM.
// Skewed pipeline: iter t computes S(t) then PV(t-1).
__global__ __launch_bounds__(256, 2) void attn_kernel(
    const float* __restrict__ x, const float* __restrict__ gamma,
    float* __restrict__ out)
{
    extern __shared__ __align__(1024) char smem[];
    AttnCtx cx;
    cx.sb = smem_u32(smem);
    cx.tid = threadIdx.x;
    cx.lane = cx.tid & 31;
    cx.warp = cx.tid >> 5;
    cx.rr = cx.lane & 7;
    cx.mat = cx.lane >> 3;
    cx.mr = (cx.warp >> 1) * 16;
    cx.jb = (cx.warp & 1) * 64;
    cx.cb = cx.warp * 32;
    const int jh = cx.warp & 1;
    const int i0 = blockIdx.x * BI;
    const int b  = blockIdx.y;

    const char* Qtb = (const char*)(g_Qt + (size_t)b * N_ * D_);
    const char* Ktb = (const char*)(g_Kt + (size_t)b * N_ * D_);
    const char* Vb  = (const char*)(g_V  + (size_t)b * C_ * N_);

    // ---- pre-loop staging: {Q, K0} group, {V0} group ----
    {
        int row = cx.tid >> 2, ch = cx.tid & 3;
        cpa16(cx.sb + SM_Q + row * 64 + (((ch ^ row) & 3) << 4),
              Qtb + (size_t)(i0 + row) * 64 + ch * 16);
        stage_K(cx, cx.sb + SM_K0, Ktb, 0);
        CP_COMMIT();
        stage_V(cx, cx.sb + SM_V, Vb, 0);
        CP_COMMIT();
    }

    float pv[64];
#pragma unroll
    for (int k = 0; k < 64; k++) pv[k] = 0.0f;
    float lacc0 = 0.0f, lacc1 = 0.0f;
    u32 aq[8];

    // ---- prologue: t = 0 (S only) ----
    {
        stage_K(cx, cx.sb + SM_K1, Ktb, BJ);
        CP_COMMIT();
        CP_WAIT(1);            // {Q,K0} + {V0} done
        __syncthreads();
#pragma unroll
        for (int kk = 0; kk < 2; kk++)
            ldsm4(aq[kk * 4 + 0], aq[kk * 4 + 1], aq[kk * 4 + 2], aq[kk * 4 + 3],
                  cx.sb + SM_Q + qkoff(cx.mr + cx.rr + ((cx.mat & 1) << 3),
                                       kk * 16 + ((cx.mat >> 1) << 3)));
        s_phase(cx, smem, cx.sb + SM_K0, SM_P0, aq, lacc0, lacc1);
    }

    // ---- steady state: t = 1..31 ----
#pragma unroll 1
    for (int t = 1; t < 32; t++) {
        const u32 kcur  = (t & 1) ? cx.sb + SM_K1 : cx.sb + SM_K0;
        const u32 knext = (t & 1) ? cx.sb + SM_K0 : cx.sb + SM_K1;
        const u32 pofs  = (t & 1) ? SM_P1 : SM_P0;
        const u32 pprev = (t & 1) ? cx.sb + SM_P0 : cx.sb + SM_P1;

        if (t < 31) { stage_K(cx, knext, Ktb, (t + 1) * BJ); CP_COMMIT(); CP_WAIT(1); }
        else        { CP_WAIT(0); }
        __syncthreads();                       // K(t) visible; P(t-1) written

        s_phase(cx, smem, kcur, pofs, aq, lacc0, lacc1);   // writes P(t)
        pv_phase(cx, pprev, cx.sb + SM_V, pv);             // consumes P(t-1), V(t-1)
        __syncthreads();                       // all warps done with V(t-1)

        stage_V(cx, cx.sb + SM_V, Vb, t * BJ);
        CP_COMMIT();
    }

    // ---- epilogue tile: PV(31) ----
    CP_WAIT(0);
    __syncthreads();
    pv_phase(cx, cx.sb + ((31 & 1) ? SM_P1 : SM_P0), cx.sb + SM_V, pv);

    // ---- softmax denominator ----
    lacc0 += __shfl_xor_sync(0xFFFFFFFFu, lacc0, 1);
    lacc0 += __shfl_xor_sync(0xFFFFFFFFu, lacc0, 2);
    lacc1 += __shfl_xor_sync(0xFFFFFFFFu, lacc1, 1);
    lacc1 += __shfl_xor_sync(0xFFFFFFFFu, lacc1, 2);
    __syncthreads();                            // pv_phase reads done before SM_L writes (aliases P1)? no: SM_L separate; sync for uniformity
    if ((cx.lane & 3) == 0) {
        const int q0 = cx.mr + (cx.lane >> 2);
        *(float*)(smem + SM_L + (q0 * 2 + jh) * 4)       = lacc0;
        *(float*)(smem + SM_L + ((q0 + 8) * 2 + jh) * 4) = lacc1;
    }
    __syncthreads();
    if (cx.tid < 64) {
        float s = *(float*)(smem + SM_L + (cx.tid * 2) * 4)
                + *(float*)(smem + SM_L + (cx.tid * 2 + 1) * 4);
        *(float*)(smem + SM_INV + cx.tid * 4) = 1.0f / s;
    }
    __syncthreads();

    // ---- epilogue: coalesced via SMEM transpose (f32 [256c][17] at smem base) ----
    const float g = gamma[0];
    const float* xb = x   + ((size_t)b * C_) * N_ + i0;
    float*       ob = out + ((size_t)b * C_) * N_ + i0;

#pragma unroll 1
    for (int qblk = 0; qblk < 4; qblk++) {
        const int mt = qblk;
#pragma unroll
        for (int np = 0; np < 2; np++)
#pragma unroll
            for (int h = 0; h < 2; h++)
#pragma unroll
                for (int e2 = 0; e2 < 2; e2++) {
                    int qloc = (cx.lane >> 2) + e2 * 8;
                    int c = cx.cb + np * 16 + h * 8 + (cx.lane & 3) * 2;
                    float il = *(const float*)(smem + SM_INV + (qblk * 16 + qloc) * 4);
                    float v0 = pv[(mt * 4 + np * 2 + h) * 4 + e2 * 2 + 0];
                    float v1 = pv[(mt * 4 + np * 2 + h) * 4 + e2 * 2 + 1];
                    *(float*)(smem + (c * 17 + qloc) * 4)       = g * v0 * il;
                    *(float*)(smem + ((c + 1) * 17 + qloc) * 4) = g * v1 * il;
                }
        __syncthreads();
#pragma unroll
        for (int i = 0; i < 16; i++) {
            int e = i * 256 + cx.tid;
            int c = e >> 4, q = e & 15;
            int qg = qblk * 16 + q;
            ob[(size_t)c * N_ + qg] = *(const float*)(smem + (c * 17 + q) * 4)
                                    + xb[(size_t)c * N_ + qg];
        }
        __syncthreads();
    }
}

// ------------------------- launch -------------------------
extern "C" void kernel_launch(void* const* d_in, const int* in_sizes, int n_in,
                              void* d_out, int out_size)
{
    (void)in_sizes; (void)n_in; (void)out_size;
    const float* x     = (const float*)d_in[0];
    const float* Wq    = (const float*)d_in[1];
    const float* bq    = (const float*)d_in[2];
    const float* Wk    = (const float*)d_in[3];
    const float* bk    = (const float*)d_in[4];
    const float* Wv    = (const float*)d_in[5];
    const float* bv    = (const float*)d_in[6];
    const float* gamma = (const float*)d_in[7];
    float* out = (float*)d_out;

    cudaFuncSetAttribute(attn_kernel, cudaFuncAttributeMaxDynamicSharedMemorySize, SMEM_SZ);

    dim3 blk(256);
    proj_kernel<<<dim3(N_ / 512, 10, B_), blk>>>(x, Wq, bq, Wk, bk, Wv, bv);
    attn_kernel<<<dim3(N_ / BI, B_), blk, SMEM_SZ>>>(x, gamma, out);
}

// round 9
// speedup vs baseline: 3.1981x; 1.0458x over previous
#include <cuda_runtime.h>
#include <cuda_bf16.h>
#include <cstdint>

typedef unsigned long long u64;
typedef uint32_t u32;

#define DEV_INLINE __device__ __forceinline__

// ------------------------- constants -------------------------
static constexpr int B_ = 4;
static constexpr int C_ = 256;
static constexpr int D_ = 32;     // C/8
static constexpr int N_ = 4096;   // 64*64
static constexpr int BI = 64;     // queries per CTA
static constexpr int BJ = 128;    // keys per j-tile

// scratch (static device globals — allocation-free per harness rules)
__device__ __align__(16) __nv_bfloat16 g_Qt[B_ * N_ * D_];   // [b][n][d] transposed
__device__ __align__(16) __nv_bfloat16 g_Kt[B_ * N_ * D_];   // [b][n][d]
__device__ __align__(16) __nv_bfloat16 g_V [B_ * C_ * N_];   // [b][c][n]

// ------------------------- helpers -------------------------
DEV_INLINE u32 smem_u32(const void* p) {
    u32 a; asm("{ .reg .u64 t; cvta.to.shared.u64 t, %1; cvt.u32.u64 %0, t; }" : "=r"(a) : "l"(p));
    return a;
}
DEV_INLINE u64 pk2(float a, float b) { u64 r; asm("mov.b64 %0, {%1,%2};" : "=l"(r) : "f"(a), "f"(b)); return r; }
DEV_INLINE void upk2(u64 v, float& a, float& b) { asm("mov.b64 {%0,%1}, %2;" : "=f"(a), "=f"(b) : "l"(v)); }
DEV_INLINE void fma2(u64& d, u64 a, u64 b) { asm("fma.rn.f32x2 %0, %1, %2, %0;" : "+l"(d) : "l"(a), "l"(b)); }

DEV_INLINE void ldsm4(u32& r0, u32& r1, u32& r2, u32& r3, u32 addr) {
    asm volatile("ldmatrix.sync.aligned.m8n8.x4.shared.b16 {%0,%1,%2,%3}, [%4];"
                 : "=r"(r0), "=r"(r1), "=r"(r2), "=r"(r3) : "r"(addr));
}
DEV_INLINE void mma16816(float* c, const u32* a, u32 b0, u32 b1) {
    asm volatile(
        "mma.sync.aligned.m16n8k16.row.col.f32.bf16.bf16.f32 "
        "{%0,%1,%2,%3}, {%4,%5,%6,%7}, {%8,%9}, {%0,%1,%2,%3};"
        : "+f"(c[0]), "+f"(c[1]), "+f"(c[2]), "+f"(c[3])
        : "r"(a[0]), "r"(a[1]), "r"(a[2]), "r"(a[3]), "r"(b0), "r"(b1));
}
DEV_INLINE void cpa16(u32 dst, const void* src) {
    asm volatile("cp.async.cg.shared.global [%0], [%1], 16;" :: "r"(dst), "l"(src));
}
#define CP_COMMIT() asm volatile("cp.async.commit_group;" ::: "memory")
#define CP_WAIT(n)  asm volatile("cp.async.wait_group %0;" :: "n"(n) : "memory")

// SMEM addressing (bf16), XOR-chunk swizzle for conflict-free ldmatrix.
DEV_INLINE u32 qkoff(int row, int kcol) {
    return (u32)(row * 64 + ((((kcol >> 3) ^ row) & 3) << 4) + ((kcol & 7) << 1));
}
DEV_INLINE u32 pvoff(int row, int kcol) {
    return (u32)(row * 256 + ((((kcol >> 3) ^ (row & 7)) & 15) << 4) + ((kcol & 7) << 1));
}

// attn SMEM layout (dynamic, bytes). P double-buffered; Q aliased into P1.
static constexpr int SM_P1  = 0;        // 64 x 256B = 16 KB   (Q = first 4 KB)
static constexpr int SM_Q   = 0;
static constexpr int SM_P0  = 16384;
static constexpr int SM_K0  = 32768;
static constexpr int SM_K1  = 40960;
static constexpr int SM_V   = 49152;    // 64 KB
static constexpr int SM_L   = 114688;
static constexpr int SM_INV = 115200;
static constexpr int SMEM_SZ = 115456;

// proj SMEM layout (dynamic, bytes): Ws f32[256][34] then 2 x-chunk buffers [16][512] f32
static constexpr int PSM_WS  = 0;            // 34816 B
static constexpr int PSM_X0  = 34816;        // 32768 B
static constexpr int PSM_X1  = 67584;        // 32768 B
static constexpr int PSMEM_SZ = 100352;      // 98 KB -> 2 CTAs/SM

// ------------------------- unified projection kernel -------------------------
// grid (N/512, 10, B): y<8 -> V rows y*32; y==8 -> Q (transposed, scaled); y==9 -> K.
// x staged through SMEM in cp.async double-buffered 16-channel chunks.
__global__ __launch_bounds__(256) void proj_kernel(
    const float* __restrict__ x,
    const float* __restrict__ Wq, const float* __restrict__ bq,
    const float* __restrict__ Wk, const float* __restrict__ bk,
    const float* __restrict__ Wv, const float* __restrict__ bv)
{
    extern __shared__ __align__(16) char psm[];
    const u32 psb = smem_u32(psm);
    float* Ws = (float*)(psm + PSM_WS);              // Ws[c*34 + r]
    const u32 xbuf[2] = { psb + PSM_X0, psb + PSM_X1 };

    const int tid = threadIdx.x;
    const int nbase = blockIdx.x * 512;
    const int n0 = nbase + tid * 2;
    const int y  = blockIdx.y;
    const int b  = blockIdx.z;

    const float* W; const float* bias; int r0; float scale; int mode;
    if (y < 8)       { W = Wv; bias = bv; r0 = y * 32; scale = 1.0f;        mode = 0; }
    else if (y == 8) { W = Wq; bias = bq; r0 = 0;      scale = 1.0f/16.0f;  mode = 1; }
    else             { W = Wk; bias = bk; r0 = 0;      scale = 1.0f;        mode = 2; }

    for (int idx = tid; idx < 32 * 256; idx += 256) {
        int r = idx >> 8, c = idx & 255;
        Ws[c * 34 + r] = W[(r0 + r) * 256 + c];
    }

    const char* xb = (const char*)(x + ((size_t)b * C_) * N_ + nbase);

    // stage chunk 0 (channels 0..15): 16 rows x 2 KB; 8 x 16B per thread
    {
#pragma unroll
        for (int it = 0; it < 8; it++) {
            int idx = tid + it * 256;
            int row = idx >> 7, off = (idx & 127) << 4;
            cpa16(xbuf[0] + row * 2048 + off, xb + (size_t)row * (N_ * 4) + off);
        }
        CP_COMMIT();
    }

    u64 accA[16], accB[16];
#pragma unroll
    for (int k = 0; k < 16; k++) { accA[k] = 0ull; accB[k] = 0ull; }

#pragma unroll 1
    for (int ch = 0; ch < 16; ch++) {
        if (ch < 15) {
            const int c1 = (ch + 1) * 16;
#pragma unroll
            for (int it = 0; it < 8; it++) {
                int idx = tid + it * 256;
                int row = idx >> 7, off = (idx & 127) << 4;
                cpa16(xbuf[(ch + 1) & 1] + row * 2048 + off,
                      xb + (size_t)(c1 + row) * (N_ * 4) + off);
            }
            CP_COMMIT();
            CP_WAIT(1);
        } else {
            CP_WAIT(0);
        }
        __syncthreads();

        const char* xs = (const char*)psm + (xbuf[ch & 1] - psb);
#pragma unroll
        for (int cc = 0; cc < 16; cc++) {
            const int c = ch * 16 + cc;
            float2 v = *(const float2*)(xs + cc * 2048 + tid * 8);
            u64 a2 = pk2(v.x, v.x), b2 = pk2(v.y, v.y);
            const u64* wrow = (const u64*)&Ws[c * 34];
#pragma unroll
            for (int k = 0; k < 16; k++) { fma2(accA[k], wrow[k], a2); fma2(accB[k], wrow[k], b2); }
        }
        __syncthreads();
    }

    if (mode == 0) {
        __nv_bfloat16* ob = g_V + ((size_t)b * C_ + r0) * N_ + n0;
#pragma unroll
        for (int k = 0; k < 16; k++) {
            float alo, ahi, blo, bhi;
            upk2(accA[k], alo, ahi); upk2(accB[k], blo, bhi);
            __nv_bfloat162 p0 = __floats2bfloat162_rn(alo + bias[r0 + 2 * k], blo + bias[r0 + 2 * k]);
            __nv_bfloat162 p1 = __floats2bfloat162_rn(ahi + bias[r0 + 2 * k + 1], bhi + bias[r0 + 2 * k + 1]);
            *(u32*)&ob[(size_t)(2 * k) * N_]     = *(u32*)&p0;
            *(u32*)&ob[(size_t)(2 * k + 1) * N_] = *(u32*)&p1;
        }
    } else {
        __nv_bfloat16* base = (mode == 1) ? g_Qt : g_Kt;
#pragma unroll
        for (int half = 0; half < 2; half++) {
            const u64* acc = half ? accB : accA;
            u32 h[16];
#pragma unroll
            for (int k = 0; k < 16; k++) {
                float lo, hi; upk2(acc[k], lo, hi);
                __nv_bfloat162 p = __floats2bfloat162_rn((lo + bias[2 * k]) * scale,
                                                         (hi + bias[2 * k + 1]) * scale);
                h[k] = *(u32*)&p;
            }
            uint4* op = (uint4*)(base + ((size_t)b * N_ + n0 + half) * 32);
#pragma unroll
            for (int w = 0; w < 4; w++)
                op[w] = make_uint4(h[4 * w], h[4 * w + 1], h[4 * w + 2], h[4 * w + 3]);
        }
    }
}

// ------------------------- attention device helpers -------------------------
struct AttnCtx {
    u32 sb; int tid, lane, warp, rr, mat, mr, jb, cb;
};

DEV_INLINE void s_phase(const AttnCtx& cx, char* smem, u32 kbuf, u32 pofs,
                        const u32 aq[8], float& lacc0, float& lacc1)
{
#pragma unroll
    for (int nbp = 0; nbp < 4; nbp++) {
        const int jcol = cx.jb + nbp * 16;
        u32 bk[2][4];
#pragma unroll
        for (int kk = 0; kk < 2; kk++)
            ldsm4(bk[kk][0], bk[kk][1], bk[kk][2], bk[kk][3],
                  kbuf + qkoff(jcol + cx.rr + ((cx.mat >> 1) << 3),
                               kk * 16 + ((cx.mat & 1) << 3)));
        float s[8] = {0.f,0.f,0.f,0.f,0.f,0.f,0.f,0.f};
#pragma unroll
        for (int kk = 0; kk < 2; kk++) {
            mma16816(&s[0], &aq[kk * 4], bk[kk][0], bk[kk][1]);
            mma16816(&s[4], &aq[kk * 4], bk[kk][2], bk[kk][3]);
        }
        const int q0 = cx.mr + (cx.lane >> 2);
#pragma unroll
        for (int h2 = 0; h2 < 2; h2++) {
            float e0 = __expf(s[h2 * 4 + 0]);
            float e1 = __expf(s[h2 * 4 + 1]);
            float e2 = __expf(s[h2 * 4 + 2]);
            float e3 = __expf(s[h2 * 4 + 3]);
            lacc0 += e0 + e1;
            lacc1 += e2 + e3;
            const int jc = jcol + h2 * 8 + (cx.lane & 3) * 2;
            __nv_bfloat162 p01 = __floats2bfloat162_rn(e0, e1);
            __nv_bfloat162 p23 = __floats2bfloat162_rn(e2, e3);
            *(u32*)(smem + pofs + pvoff(q0,     jc)) = *(u32*)&p01;
            *(u32*)(smem + pofs + pvoff(q0 + 8, jc)) = *(u32*)&p23;
        }
    }
}

DEV_INLINE void pv_phase(const AttnCtx& cx, u32 pbuf, u32 vbuf, float pv[64])
{
#pragma unroll
    for (int kk = 0; kk < 8; kk++) {
        u32 ap[4][4];
#pragma unroll
        for (int mt = 0; mt < 4; mt++)
            ldsm4(ap[mt][0], ap[mt][1], ap[mt][2], ap[mt][3],
                  pbuf + pvoff(mt * 16 + cx.rr + ((cx.mat & 1) << 3),
                               kk * 16 + ((cx.mat >> 1) << 3)));
#pragma unroll
        for (int np = 0; np < 2; np++) {
            u32 b0, b1, b2, b3;
            ldsm4(b0, b1, b2, b3,
                  vbuf + pvoff(cx.cb + np * 16 + cx.rr + ((cx.mat >> 1) << 3),
                               kk * 16 + ((cx.mat & 1) << 3)));
#pragma unroll
            for (int mt = 0; mt < 4; mt++) {
                mma16816(&pv[(mt * 4 + np * 2) * 4],     ap[mt], b0, b1);
                mma16816(&pv[(mt * 4 + np * 2 + 1) * 4], ap[mt], b2, b3);
            }
        }
    }
}

DEV_INLINE void stage_K(const AttnCtx& cx, u32 kbuf, const char* Ktb, int j0) {
#pragma unroll
    for (int it = 0; it < 2; it++) {
        int idx = cx.tid + it * 256;
        int kr = idx >> 2, kc = idx & 3;
        cpa16(kbuf + kr * 64 + (((kc ^ kr) & 3) << 4),
              Ktb + (size_t)(j0 + kr) * 64 + kc * 16);
    }
}
DEV_INLINE void stage_V(const AttnCtx& cx, u32 vbuf, const char* Vb, int j0) {
#pragma unroll
    for (int it = 0; it < 16; it++) {
        int idx = cx.tid + it * 256;
        int c = idx >> 4, vc = idx & 15;
        cpa16(vbuf + c * 256 + ((vc ^ (c & 7)) << 4),
              Vb + (size_t)c * (N_ * 2) + (size_t)j0 * 2 + vc * 16);
    }
}

// ------------------------- attention kernel -------------------------
// grid (N/64, B), 256 threads (8 warps), 2 CTAs/SM.
// Skewed pipeline: iter t computes S(t) then PV(t-1).
__global__ __launch_bounds__(256, 2) void attn_kernel(
    const float* __restrict__ x, const float* __restrict__ gamma,
    float* __restrict__ out)
{
    extern __shared__ __align__(1024) char smem[];
    AttnCtx cx;
    cx.sb = smem_u32(smem);
    cx.tid = threadIdx.x;
    cx.lane = cx.tid & 31;
    cx.warp = cx.tid >> 5;
    cx.rr = cx.lane & 7;
    cx.mat = cx.lane >> 3;
    cx.mr = (cx.warp >> 1) * 16;
    cx.jb = (cx.warp & 1) * 64;
    cx.cb = cx.warp * 32;
    const int jh = cx.warp & 1;
    const int i0 = blockIdx.x * BI;
    const int b  = blockIdx.y;

    const char* Qtb = (const char*)(g_Qt + (size_t)b * N_ * D_);
    const char* Ktb = (const char*)(g_Kt + (size_t)b * N_ * D_);
    const char* Vb  = (const char*)(g_V  + (size_t)b * C_ * N_);

    // ---- pre-loop staging: {Q, K0} group, {V0} group ----
    {
        int row = cx.tid >> 2, ch = cx.tid & 3;
        cpa16(cx.sb + SM_Q + row * 64 + (((ch ^ row) & 3) << 4),
              Qtb + (size_t)(i0 + row) * 64 + ch * 16);
        stage_K(cx, cx.sb + SM_K0, Ktb, 0);
        CP_COMMIT();
        stage_V(cx, cx.sb + SM_V, Vb, 0);
        CP_COMMIT();
    }

    float pv[64];
#pragma unroll
    for (int k = 0; k < 64; k++) pv[k] = 0.0f;
    float lacc0 = 0.0f, lacc1 = 0.0f;
    u32 aq[8];

    // ---- prologue: t = 0 (S only) ----
    {
        stage_K(cx, cx.sb + SM_K1, Ktb, BJ);
        CP_COMMIT();
        CP_WAIT(1);            // {Q,K0} + {V0} done
        __syncthreads();
#pragma unroll
        for (int kk = 0; kk < 2; kk++)
            ldsm4(aq[kk * 4 + 0], aq[kk * 4 + 1], aq[kk * 4 + 2], aq[kk * 4 + 3],
                  cx.sb + SM_Q + qkoff(cx.mr + cx.rr + ((cx.mat & 1) << 3),
                                       kk * 16 + ((cx.mat >> 1) << 3)));
        s_phase(cx, smem, cx.sb + SM_K0, SM_P0, aq, lacc0, lacc1);
    }

    // ---- steady state: t = 1..31 ----
#pragma unroll 1
    for (int t = 1; t < 32; t++) {
        const u32 kcur  = (t & 1) ? cx.sb + SM_K1 : cx.sb + SM_K0;
        const u32 knext = (t & 1) ? cx.sb + SM_K0 : cx.sb + SM_K1;
        const u32 pofs  = (t & 1) ? SM_P1 : SM_P0;
        const u32 pprev = (t & 1) ? cx.sb + SM_P0 : cx.sb + SM_P1;

        if (t < 31) { stage_K(cx, knext, Ktb, (t + 1) * BJ); CP_COMMIT(); CP_WAIT(1); }
        else        { CP_WAIT(0); }
        __syncthreads();                       // K(t) visible; P(t-1) written

        s_phase(cx, smem, kcur, pofs, aq, lacc0, lacc1);   // writes P(t)
        pv_phase(cx, pprev, cx.sb + SM_V, pv);             // consumes P(t-1), V(t-1)
        __syncthreads();                       // all warps done with V(t-1)

        stage_V(cx, cx.sb + SM_V, Vb, t * BJ);
        CP_COMMIT();
    }

    // ---- epilogue tile: PV(31) ----
    CP_WAIT(0);
    __syncthreads();
    pv_phase(cx, cx.sb + SM_P1, cx.sb + SM_V, pv);

    // ---- softmax denominator ----
    lacc0 += __shfl_xor_sync(0xFFFFFFFFu, lacc0, 1);
    lacc0 += __shfl_xor_sync(0xFFFFFFFFu, lacc0, 2);
    lacc1 += __shfl_xor_sync(0xFFFFFFFFu, lacc1, 1);
    lacc1 += __shfl_xor_sync(0xFFFFFFFFu, lacc1, 2);
    __syncthreads();
    if ((cx.lane & 3) == 0) {
        const int q0 = cx.mr + (cx.lane >> 2);
        *(float*)(smem + SM_L + (q0 * 2 + jh) * 4)       = lacc0;
        *(float*)(smem + SM_L + ((q0 + 8) * 2 + jh) * 4) = lacc1;
    }
    __syncthreads();
    if (cx.tid < 64) {
        float s = *(float*)(smem + SM_L + (cx.tid * 2) * 4)
                + *(float*)(smem + SM_L + (cx.tid * 2 + 1) * 4);
        *(float*)(smem + SM_INV + cx.tid * 4) = 1.0f / s;
    }
    __syncthreads();

    // ---- epilogue: coalesced via SMEM transpose (f32 [256c][17] at smem base) ----
    const float g = gamma[0];
    const float* xb = x   + ((size_t)b * C_) * N_ + i0;
    float*       ob = out + ((size_t)b * C_) * N_ + i0;

#pragma unroll 1
    for (int qblk = 0; qblk < 4; qblk++) {
        const int mt = qblk;
#pragma unroll
        for (int np = 0; np < 2; np++)
#pragma unroll
            for (int h = 0; h < 2; h++)
#pragma unroll
                for (int e2 = 0; e2 < 2; e2++) {
                    int qloc = (cx.lane >> 2) + e2 * 8;
                    int c = cx.cb + np * 16 + h * 8 + (cx.lane & 3) * 2;
                    float il = *(const float*)(smem + SM_INV + (qblk * 16 + qloc) * 4);
                    float v0 = pv[(mt * 4 + np * 2 + h) * 4 + e2 * 2 + 0];
                    float v1 = pv[(mt * 4 + np * 2 + h) * 4 + e2 * 2 + 1];
                    *(float*)(smem + (c * 17 + qloc) * 4)       = g * v0 * il;
                    *(float*)(smem + ((c + 1) * 17 + qloc) * 4) = g * v1 * il;
                }
        __syncthreads();
#pragma unroll
        for (int i = 0; i < 16; i++) {
            int e = i * 256 + cx.tid;
            int c = e >> 4, q = e & 15;
            int qg = qblk * 16 + q;
            ob[(size_t)c * N_ + qg] = *(const float*)(smem + (c * 17 + q) * 4)
                                    + xb[(size_t)c * N_ + qg];
        }
        __syncthreads();
    }
}

// ------------------------- launch -------------------------
extern "C" void kernel_launch(void* const* d_in, const int* in_sizes, int n_in,
                              void* d_out, int out_size)
{
    (void)in_sizes; (void)n_in; (void)out_size;
    const float* x     = (const float*)d_in[0];
    const float* Wq    = (const float*)d_in[1];
    const float* bq    = (const float*)d_in[2];
    const float* Wk    = (const float*)d_in[3];
    const float* bk    = (const float*)d_in[4];
    const float* Wv    = (const float*)d_in[5];
    const float* bv    = (const float*)d_in[6];
    const float* gamma = (const float*)d_in[7];
    float* out = (float*)d_out;

    cudaFuncSetAttribute(proj_kernel, cudaFuncAttributeMaxDynamicSharedMemorySize, PSMEM_SZ);
    cudaFuncSetAttribute(attn_kernel, cudaFuncAttributeMaxDynamicSharedMemorySize, SMEM_SZ);

    dim3 blk(256);
    proj_kernel<<<dim3(N_ / 512, 10, B_), blk, PSMEM_SZ>>>(x, Wq, bq, Wk, bk, Wv, bv);
    attn_kernel<<<dim3(N_ / BI, B_), blk, SMEM_SZ>>>(x, gamma, out);
}

// round 10
// speedup vs baseline: 3.2992x; 1.0316x over previous
#include <cuda_runtime.h>
#include <cuda_bf16.h>
#include <cstdint>

typedef unsigned long long u64;
typedef uint32_t u32;
typedef unsigned short u16;
typedef unsigned char u8;

#define DEV_INLINE __device__ __forceinline__

// ------------------------- constants -------------------------
static constexpr int B_ = 4;
static constexpr int C_ = 256;
static constexpr int D_ = 32;     // C/8
static constexpr int N_ = 4096;   // 64*64
static constexpr int BI = 64;     // queries per CTA
static constexpr int BJ = 256;    // keys per j-tile (fp8 -> bigger tile, fewer syncs)
static constexpr int NT = N_ / BJ; // 16 tiles

// exp scale: 1/sqrt(C) folded into exp2 argument (Q stored UNSCALED for e4m3 range)
#define EXP_SCL 0.09016843980556022f   // log2(e)/16

// fp8 scratch (static device globals — allocation-free per harness rules)
__device__ __align__(16) u8 g_Qt8[B_ * N_ * 32];   // [b][n][32d] e4m3, 32B rows
__device__ __align__(16) u8 g_Kt8[B_ * N_ * 32];   // [b][n][32d]
__device__ __align__(16) u8 g_V8 [B_ * C_ * N_];   // [b][c][n]  e4m3

// ------------------------- helpers -------------------------
DEV_INLINE u32 smem_u32(const void* p) {
    u32 a; asm("{ .reg .u64 t; cvta.to.shared.u64 t, %1; cvt.u32.u64 %0, t; }" : "=r"(a) : "l"(p));
    return a;
}
DEV_INLINE u64 pk2(float a, float b) { u64 r; asm("mov.b64 %0, {%1,%2};" : "=l"(r) : "f"(a), "f"(b)); return r; }
DEV_INLINE void upk2(u64 v, float& a, float& b) { asm("mov.b64 {%0,%1}, %2;" : "=f"(a), "=f"(b) : "l"(v)); }
DEV_INLINE void fma2(u64& d, u64 a, u64 b) { asm("fma.rn.f32x2 %0, %1, %2, %0;" : "+l"(d) : "l"(a), "l"(b)); }

DEV_INLINE void ldsm4(u32& r0, u32& r1, u32& r2, u32& r3, u32 addr) {
    asm volatile("ldmatrix.sync.aligned.m8n8.x4.shared.b16 {%0,%1,%2,%3}, [%4];"
                 : "=r"(r0), "=r"(r1), "=r"(r2), "=r"(r3) : "r"(addr));
}
// fp8 e4m3 mma: D(f32) = A(16x32 e4m3) * B(8x32 e4m3)^T + D
DEV_INLINE void mmafp8(float* c, const u32* a, u32 b0, u32 b1) {
    asm volatile(
        "mma.sync.aligned.m16n8k32.row.col.f32.e4m3.e4m3.f32 "
        "{%0,%1,%2,%3}, {%4,%5,%6,%7}, {%8,%9}, {%0,%1,%2,%3};"
        : "+f"(c[0]), "+f"(c[1]), "+f"(c[2]), "+f"(c[3])
        : "r"(a[0]), "r"(a[1]), "r"(a[2]), "r"(a[3]), "r"(b0), "r"(b1));
}
DEV_INLINE u16 e4m3x2(float hi, float lo) {
    u16 r; asm("cvt.rn.satfinite.e4m3x2.f32 %0, %1, %2;" : "=h"(r) : "f"(hi), "f"(lo)); return r;
}
DEV_INLINE float ex2f(float s) {
    float e; asm("ex2.approx.ftz.f32 %0, %1;" : "=f"(e) : "f"(s)); return e;
}
DEV_INLINE void cpa16(u32 dst, const void* src) {
    asm volatile("cp.async.cg.shared.global [%0], [%1], 16;" :: "r"(dst), "l"(src));
}
#define CP_COMMIT() asm volatile("cp.async.commit_group;" ::: "memory")
#define CP_WAIT(n)  asm volatile("cp.async.wait_group %0;" :: "n"(n) : "memory")

// Q/K tiles: 32B rows (32 e4m3 of d); 16B chunk ^= row>>2 (conflict-free ldsm)
DEV_INLINE u32 kswz(int row, int c) { return (u32)(row * 32 + (((c ^ (row >> 2)) & 1) << 4)); }
// V/P tiles: 256B rows (256 e4m3 of j); 16B chunk(0..15) ^= row&7
DEV_INLINE u32 vswz(int row, int ch) { return (u32)(row * 256 + ((ch ^ (row & 7)) << 4)); }

// attn SMEM layout (dynamic, bytes). P double-buffered; Q aliased into P1
// (Q consumed into registers at t=0; P1 first written at t=1).
static constexpr int SM_P1  = 0;        // 64 x 256B = 16 KB  (Q = first 2 KB)
static constexpr int SM_Q   = 0;
static constexpr int SM_P0  = 16384;    // 64 x 256B
static constexpr int SM_K0  = 32768;    // 256 x 32B = 8 KB
static constexpr int SM_K1  = 40960;
static constexpr int SM_V   = 49152;    // 256 x 256B = 64 KB (single buffer)
static constexpr int SM_L   = 114688;   // float[64][2]
static constexpr int SM_INV = 115200;   // float[64]
static constexpr int SMEM_SZ = 115456;  // x2 CTAs/SM

// proj SMEM: Ws f32[256][34] + 2 x-chunk buffers [16ch][512n] f32
static constexpr int PSM_WS  = 0;
static constexpr int PSM_X0  = 34816;
static constexpr int PSM_X1  = 67584;
static constexpr int PSMEM_SZ = 100352;

// ------------------------- unified projection kernel -------------------------
// grid (N/512, 10, B): y<8 -> V rows y*32 (e4m3 [c][n]); y==8 -> Q; y==9 -> K
// (both transposed [n][32] e4m3, UNSCALED). x staged via cp.async double buffers.
__global__ __launch_bounds__(256) void proj_kernel(
    const float* __restrict__ x,
    const float* __restrict__ Wq, const float* __restrict__ bq,
    const float* __restrict__ Wk, const float* __restrict__ bk,
    const float* __restrict__ Wv, const float* __restrict__ bv)
{
    extern __shared__ __align__(16) char psm[];
    const u32 psb = smem_u32(psm);
    float* Ws = (float*)(psm + PSM_WS);
    const u32 xbuf[2] = { psb + PSM_X0, psb + PSM_X1 };

    const int tid = threadIdx.x;
    const int nbase = blockIdx.x * 512;
    const int n0 = nbase + tid * 2;
    const int y  = blockIdx.y;
    const int b  = blockIdx.z;

    const float* W; const float* bias; int r0; int mode;
    if (y < 8)       { W = Wv; bias = bv; r0 = y * 32; mode = 0; }
    else if (y == 8) { W = Wq; bias = bq; r0 = 0;      mode = 1; }
    else             { W = Wk; bias = bk; r0 = 0;      mode = 2; }

    for (int idx = tid; idx < 32 * 256; idx += 256) {
        int r = idx >> 8, c = idx & 255;
        Ws[c * 34 + r] = W[(r0 + r) * 256 + c];
    }

    const char* xb = (const char*)(x + ((size_t)b * C_) * N_ + nbase);
    {
#pragma unroll
        for (int it = 0; it < 8; it++) {
            int idx = tid + it * 256;
            int row = idx >> 7, off = (idx & 127) << 4;
            cpa16(xbuf[0] + row * 2048 + off, xb + (size_t)row * (N_ * 4) + off);
        }
        CP_COMMIT();
    }

    u64 accA[16], accB[16];
#pragma unroll
    for (int k = 0; k < 16; k++) { accA[k] = 0ull; accB[k] = 0ull; }

#pragma unroll 1
    for (int ch = 0; ch < 16; ch++) {
        if (ch < 15) {
            const int c1 = (ch + 1) * 16;
#pragma unroll
            for (int it = 0; it < 8; it++) {
                int idx = tid + it * 256;
                int row = idx >> 7, off = (idx & 127) << 4;
                cpa16(xbuf[(ch + 1) & 1] + row * 2048 + off,
                      xb + (size_t)(c1 + row) * (N_ * 4) + off);
            }
            CP_COMMIT();
            CP_WAIT(1);
        } else {
            CP_WAIT(0);
        }
        __syncthreads();

        const char* xs = (const char*)psm + (xbuf[ch & 1] - psb);
#pragma unroll
        for (int cc = 0; cc < 16; cc++) {
            const int c = ch * 16 + cc;
            float2 v = *(const float2*)(xs + cc * 2048 + tid * 8);
            u64 a2 = pk2(v.x, v.x), b2 = pk2(v.y, v.y);
            const u64* wrow = (const u64*)&Ws[c * 34];
#pragma unroll
            for (int k = 0; k < 16; k++) { fma2(accA[k], wrow[k], a2); fma2(accB[k], wrow[k], b2); }
        }
        __syncthreads();
    }

    if (mode == 0) {
        u8* ob = g_V8 + ((size_t)b * C_ + r0) * N_ + n0;
#pragma unroll
        for (int k = 0; k < 16; k++) {
            float alo, ahi, blo, bhi;
            upk2(accA[k], alo, ahi); upk2(accB[k], blo, bhi);
            float b0 = bias[r0 + 2 * k], b1 = bias[r0 + 2 * k + 1];
            *(u16*)(ob + (size_t)(2 * k) * N_)     = e4m3x2(blo + b0, alo + b0);
            *(u16*)(ob + (size_t)(2 * k + 1) * N_) = e4m3x2(bhi + b1, ahi + b1);
        }
    } else {
        u8* base = (mode == 1) ? g_Qt8 : g_Kt8;
#pragma unroll
        for (int half = 0; half < 2; half++) {
            const u64* acc = half ? accB : accA;
            u32 h[8];
#pragma unroll
            for (int j = 0; j < 8; j++) {
                float l0, h0, l1, h1;
                upk2(acc[2 * j], l0, h0); upk2(acc[2 * j + 1], l1, h1);
                u16 wa = e4m3x2(h0 + bias[4 * j + 1], l0 + bias[4 * j]);
                u16 wb = e4m3x2(h1 + bias[4 * j + 3], l1 + bias[4 * j + 2]);
                h[j] = (u32)wa | ((u32)wb << 16);
            }
            uint4* op = (uint4*)(base + ((size_t)b * N_ + n0 + half) * 32);
            op[0] = make_uint4(h[0], h[1], h[2], h[3]);
            op[1] = make_uint4(h[4], h[5], h[6], h[7]);
        }
    }
}

// ------------------------- attention device helpers -------------------------
struct AttnCtx {
    u32 sb; int tid, lane, warp, rr, mat, mr, jb, cb;
};

// S = Q.K^T (warp: 16q x 128j), exp, e4m3 P write, l accumulate
DEV_INLINE void s_phase(const AttnCtx& cx, char* smem, u32 kbuf, u32 pofs,
                        const u32 aq[4], float& lacc0, float& lacc1)
{
    const int q0 = cx.mr + (cx.lane >> 2);
    const int jl = 2 * (cx.lane & 3);
    const u32 prow0 = pofs + q0 * 256 + ((q0 & 7) << 4);        // chunk pre-xored below
    const u32 prow8 = prow0 + 8 * 256;
#pragma unroll
    for (int nbp = 0; nbp < 8; nbp++) {
        const int jcol = cx.jb + nbp * 16;
        const int rowB = jcol + ((cx.mat >> 1) << 3) + cx.rr;
        u32 b0, b1, b2, b3;
        ldsm4(b0, b1, b2, b3, kbuf + kswz(rowB, cx.mat & 1));
        float s[8] = {0.f,0.f,0.f,0.f,0.f,0.f,0.f,0.f};
        mmafp8(&s[0], aq, b0, b1);
        mmafp8(&s[4], aq, b2, b3);
        float e0 = ex2f(s[0] * EXP_SCL), e1 = ex2f(s[1] * EXP_SCL);
        float e2 = ex2f(s[2] * EXP_SCL), e3 = ex2f(s[3] * EXP_SCL);
        float e4 = ex2f(s[4] * EXP_SCL), e5 = ex2f(s[5] * EXP_SCL);
        float e6 = ex2f(s[6] * EXP_SCL), e7 = ex2f(s[7] * EXP_SCL);
        lacc0 += (e0 + e1) + (e4 + e5);
        lacc1 += (e2 + e3) + (e6 + e7);
        const u32 csw = (u32)(((jcol >> 4) ^ (q0 & 7)) << 4) - (u32)((q0 & 7) << 4);
        *(u16*)(smem + prow0 + csw + jl)     = e4m3x2(e1, e0);
        *(u16*)(smem + prow0 + csw + jl + 8) = e4m3x2(e5, e4);
        *(u16*)(smem + prow8 + csw + jl)     = e4m3x2(e3, e2);
        *(u16*)(smem + prow8 + csw + jl + 8) = e4m3x2(e7, e6);
    }
}

// O += P.V^T (warp: 64q x 32c, K = 256 j)
DEV_INLINE void pv_phase(const AttnCtx& cx, u32 pbuf, u32 vbuf, float pv[64])
{
#pragma unroll
    for (int kk = 0; kk < 8; kk++) {
        u32 ap[4][4];
#pragma unroll
        for (int mt = 0; mt < 4; mt++) {
            const int rowA = mt * 16 + ((cx.mat & 1) << 3) + cx.rr;
            ldsm4(ap[mt][0], ap[mt][1], ap[mt][2], ap[mt][3],
                  pbuf + vswz(rowA, kk * 2 + (cx.mat >> 1)));
        }
#pragma unroll
        for (int np = 0; np < 2; np++) {
            const int rowV = cx.cb + np * 16 + ((cx.mat >> 1) << 3) + cx.rr;
            u32 b0, b1, b2, b3;
            ldsm4(b0, b1, b2, b3, vbuf + vswz(rowV, kk * 2 + (cx.mat & 1)));
#pragma unroll
            for (int mt = 0; mt < 4; mt++) {
                mmafp8(&pv[(mt * 4 + np * 2) * 4],     ap[mt], b0, b1);
                mmafp8(&pv[(mt * 4 + np * 2 + 1) * 4], ap[mt], b2, b3);
            }
        }
    }
}

DEV_INLINE void stage_K(const AttnCtx& cx, u32 kbuf, const u8* Ktb, int j0) {
#pragma unroll
    for (int it = 0; it < 2; it++) {
        int idx = cx.tid + it * 256;
        int row = idx >> 1, c = idx & 1;
        cpa16(kbuf + kswz(row, c), Ktb + (size_t)(j0 + row) * 32 + c * 16);
    }
}
DEV_INLINE void stage_V(const AttnCtx& cx, u32 vbuf, const u8* Vb, int j0) {
#pragma unroll
    for (int it = 0; it < 16; it++) {
        int idx = cx.tid + it * 256;
        int row = idx >> 4, ch = idx & 15;
        cpa16(vbuf + vswz(row, ch), Vb + (size_t)row * N_ + j0 + ch * 16);
    }
}

// ------------------------- attention kernel -------------------------
// grid (N/64, B), 256 threads (8 warps), 2 CTAs/SM, fp8 operands.
// Skewed pipeline: iter t computes S(t) then PV(t-1). NT=16 tiles of 256 j.
__global__ __launch_bounds__(256, 2) void attn_kernel(
    const float* __restrict__ x, const float* __restrict__ gamma,
    float* __restrict__ out)
{
    extern __shared__ __align__(1024) char smem[];
    AttnCtx cx;
    cx.sb = smem_u32(smem);
    cx.tid = threadIdx.x;
    cx.lane = cx.tid & 31;
    cx.warp = cx.tid >> 5;
    cx.rr = cx.lane & 7;
    cx.mat = cx.lane >> 3;
    cx.mr = (cx.warp >> 1) * 16;
    cx.jb = (cx.warp & 1) * 128;
    cx.cb = cx.warp * 32;
    const int jh = cx.warp & 1;
    const int i0 = blockIdx.x * BI;
    const int b  = blockIdx.y;

    const u8* Qtb = g_Qt8 + (size_t)b * N_ * 32;
    const u8* Ktb = g_Kt8 + (size_t)b * N_ * 32;
    const u8* Vb  = g_V8  + (size_t)b * C_ * N_;

    // ---- pre-loop staging: {Q, K0} group, {V0} group ----
    {
        if (cx.tid < 128) {
            int row = cx.tid >> 1, c = cx.tid & 1;
            cpa16(cx.sb + SM_Q + kswz(row, c), Qtb + (size_t)(i0 + row) * 32 + c * 16);
        }
        stage_K(cx, cx.sb + SM_K0, Ktb, 0);
        CP_COMMIT();
        stage_V(cx, cx.sb + SM_V, Vb, 0);
        CP_COMMIT();
    }

    float pv[64];
#pragma unroll
    for (int k = 0; k < 64; k++) pv[k] = 0.0f;
    float lacc0 = 0.0f, lacc1 = 0.0f;
    u32 aq[4];

    // ---- prologue: t = 0 (S only) ----
    {
        stage_K(cx, cx.sb + SM_K1, Ktb, BJ);
        CP_COMMIT();
        CP_WAIT(1);            // {Q,K0} + {V0} done
        __syncthreads();
        const int rowA = cx.mr + ((cx.mat & 1) << 3) + cx.rr;
        ldsm4(aq[0], aq[1], aq[2], aq[3], cx.sb + SM_Q + kswz(rowA, cx.mat >> 1));
        s_phase(cx, smem, cx.sb + SM_K0, SM_P0, aq, lacc0, lacc1);
    }

    // ---- steady state: t = 1..NT-1 ----
#pragma unroll 1
    for (int t = 1; t < NT; t++) {
        const u32 kcur  = (t & 1) ? cx.sb + SM_K1 : cx.sb + SM_K0;
        const u32 knext = (t & 1) ? cx.sb + SM_K0 : cx.sb + SM_K1;
        const u32 pofs  = (t & 1) ? SM_P1 : SM_P0;
        const u32 pprev = (t & 1) ? cx.sb + SM_P0 : cx.sb + SM_P1;

        if (t < NT - 1) { stage_K(cx, knext, Ktb, (t + 1) * BJ); CP_COMMIT(); CP_WAIT(1); }
        else            { CP_WAIT(0); }
        __syncthreads();                       // K(t) visible; P(t-1) written

        s_phase(cx, smem, kcur, pofs, aq, lacc0, lacc1);   // writes P(t)
        pv_phase(cx, pprev, cx.sb + SM_V, pv);             // consumes P(t-1), V(t-1)
        __syncthreads();                       // all warps done with V(t-1)

        stage_V(cx, cx.sb + SM_V, Vb, t * BJ);
        CP_COMMIT();
    }

    // ---- epilogue tile: PV(NT-1) ----
    CP_WAIT(0);
    __syncthreads();
    pv_phase(cx, cx.sb + SM_P1, cx.sb + SM_V, pv);   // NT-1 = 15 odd -> P1

    // ---- softmax denominator ----
    lacc0 += __shfl_xor_sync(0xFFFFFFFFu, lacc0, 1);
    lacc0 += __shfl_xor_sync(0xFFFFFFFFu, lacc0, 2);
    lacc1 += __shfl_xor_sync(0xFFFFFFFFu, lacc1, 1);
    lacc1 += __shfl_xor_sync(0xFFFFFFFFu, lacc1, 2);
    __syncthreads();                           // all pv_phase reads done
    if ((cx.lane & 3) == 0) {
        const int q0 = cx.mr + (cx.lane >> 2);
        *(float*)(smem + SM_L + (q0 * 2 + jh) * 4)       = lacc0;
        *(float*)(smem + SM_L + ((q0 + 8) * 2 + jh) * 4) = lacc1;
    }
    __syncthreads();
    if (cx.tid < 64) {
        float s = *(float*)(smem + SM_L + (cx.tid * 2) * 4)
                + *(float*)(smem + SM_L + (cx.tid * 2 + 1) * 4);
        *(float*)(smem + SM_INV + cx.tid * 4) = 1.0f / s;
    }
    __syncthreads();

    // ---- epilogue: coalesced via SMEM transpose (f32 [256c][17] at smem base) ----
    const float g = gamma[0];
    const float* xb = x   + ((size_t)b * C_) * N_ + i0;
    float*       ob = out + ((size_t)b * C_) * N_ + i0;

#pragma unroll 1
    for (int qblk = 0; qblk < 4; qblk++) {
        const int mt = qblk;
#pragma unroll
        for (int np = 0; np < 2; np++)
#pragma unroll
            for (int h = 0; h < 2; h++)
#pragma unroll
                for (int e2 = 0; e2 < 2; e2++) {
                    int qloc = (cx.lane >> 2) + e2 * 8;
                    int c = cx.cb + np * 16 + h * 8 + (cx.lane & 3) * 2;
                    float il = *(const float*)(smem + SM_INV + (qblk * 16 + qloc) * 4);
                    float v0 = pv[(mt * 4 + np * 2 + h) * 4 + e2 * 2 + 0];
                    float v1 = pv[(mt * 4 + np * 2 + h) * 4 + e2 * 2 + 1];
                    *(float*)(smem + (c * 17 + qloc) * 4)       = g * v0 * il;
                    *(float*)(smem + ((c + 1) * 17 + qloc) * 4) = g * v1 * il;
                }
        __syncthreads();
#pragma unroll
        for (int i = 0; i < 16; i++) {
            int e = i * 256 + cx.tid;
            int c = e >> 4, q = e & 15;
            int qg = qblk * 16 + q;
            ob[(size_t)c * N_ + qg] = *(const float*)(smem + (c * 17 + q) * 4)
                                    + xb[(size_t)c * N_ + qg];
        }
        __syncthreads();
    }
}

// ------------------------- launch -------------------------
extern "C" void kernel_launch(void* const* d_in, const int* in_sizes, int n_in,
                              void* d_out, int out_size)
{
    (void)in_sizes; (void)n_in; (void)out_size;
    const float* x     = (const float*)d_in[0];
    const float* Wq    = (const float*)d_in[1];
    const float* bq    = (const float*)d_in[2];
    const float* Wk    = (const float*)d_in[3];
    const float* bk    = (const float*)d_in[4];
    const float* Wv    = (const float*)d_in[5];
    const float* bv    = (const float*)d_in[6];
    const float* gamma = (const float*)d_in[7];
    float* out = (float*)d_out;

    cudaFuncSetAttribute(proj_kernel, cudaFuncAttributeMaxDynamicSharedMemorySize, PSMEM_SZ);
    cudaFuncSetAttribute(attn_kernel, cudaFuncAttributeMaxDynamicSharedMemorySize, SMEM_SZ);

    dim3 blk(256);
    proj_kernel<<<dim3(N_ / 512, 10, B_), blk, PSMEM_SZ>>>(x, Wq, bq, Wk, bk, Wv, bv);
    attn_kernel<<<dim3(N_ / BI, B_), blk, SMEM_SZ>>>(x, gamma, out);
}